// round 13
// baseline (speedup 1.0000x reference)
#include <cuda_runtime.h>
#include <cuda_bf16.h>
#include <mma.h>
#include <cstdint>

using namespace nvcuda;

#define B_ 256
#define I_ 512
#define R_ 512
#define A_ 196
#define V_ 10000

// ================= scratch (static device; no allocation allowed) =================
__device__ float g_ah[B_ * A_];            // [B, A]
__device__ float g_spart[B_ * A_ * 4];     // attend0 score partials (2 nblocks x 2 halves)
__device__ float g_score1[B_ * A_];        // attend1 scores
__device__ float g_w[B_ * A_];             // softmax weights
__device__ float g_av1[B_ * A_ * 256];     // raw att.Wa2a1^T (padded N=256), 51.4MB
__device__ float g_attres[B_ * R_];        // [B, R]
__device__ float g_sums[3][B_ * 4 * R_];   // per-phase gate GEMM results
__device__ float g_nexth[B_ * R_];         // [B, R]
__device__ float g_bias[4 * R_];           // combined gate bias

// split-bf16 weight caches
__device__ __nv_bfloat16 g_Wa2a_h[A_ * R_],  g_Wa2a_l[A_ * R_];
__device__ __nv_bfloat16 g_Wa2a1_h[A_ * R_], g_Wa2a1_l[A_ * R_];
__device__ __nv_bfloat16 g_Wi_h[4 * R_ * I_], g_Wi_l[4 * R_ * I_];
__device__ __nv_bfloat16 g_Wh_h[4 * R_ * R_], g_Wh_l[4 * R_ * R_];
__device__ __nv_bfloat16 g_Wah_h[4 * R_ * R_], g_Wah_l[4 * R_ * R_];
__device__ __nv_bfloat16 g_Wp_h[V_ * R_], g_Wp_l[V_ * R_];

// smem staging (bf16 elems, ld = 40); tile = 128x32 = 5120 elems
// A single-buffered, B double-buffered (cp.async)
#define LDT 40
#define OFF_AH  0
#define OFF_AL  5120
#define OFF_B0H 10240
#define OFF_B0L 15360
#define OFF_B1H 20480
#define OFF_B1L 25600
#define SMEM_GEMM 61440
#define SMEM_DUAL 69632   // max(staging 61440, 128x132 fp32 C tile 67584)

// pack 16 floats -> 2x uint4 hi + 2x uint4 lo (8 bf16 per uint4)
__device__ __forceinline__ void split16(const float* f, uint4* H, uint4* L) {
    __align__(16) unsigned short hs[16];
    __align__(16) unsigned short ls[16];
#pragma unroll
    for (int e = 0; e < 16; e++) {
        __nv_bfloat16 h = __float2bfloat16_rn(f[e]);
        hs[e] = __bfloat16_as_ushort(h);
        ls[e] = __bfloat16_as_ushort(__float2bfloat16_rn(f[e] - __bfloat162float(h)));
    }
    H[0] = ((uint4*)hs)[0]; H[1] = ((uint4*)hs)[1];
    L[0] = ((uint4*)ls)[0]; L[1] = ((uint4*)ls)[1];
}

__device__ __forceinline__ uint32_t smem_u32(const void* p) {
    uint32_t a;
    asm("{ .reg .u64 t; cvta.to.shared.u64 t, %1; cvt.u32.u64 %0, t; }" : "=r"(a) : "l"(p));
    return a;
}
// cp.async 16B with zero-fill when src_sz == 0
__device__ __forceinline__ void cp16(uint32_t dst, const void* src, int src_sz) {
    asm volatile("cp.async.cg.shared.global [%0], [%1], 16, %2;"
                 :: "r"(dst), "l"(src), "r"(src_sz));
}
__device__ __forceinline__ void cp_commit() { asm volatile("cp.async.commit_group;"); }
__device__ __forceinline__ void cp_wait1() { asm volatile("cp.async.wait_group 1;"); }
__device__ __forceinline__ void cp_wait0() { asm volatile("cp.async.wait_group 0;"); }

// ---- shared MMA inner step over staged tiles ----
__device__ __forceinline__ void mma_tiles(
    const __nv_bfloat16* sAH, const __nv_bfloat16* sAL,
    const __nv_bfloat16* sBH, const __nv_bfloat16* sBL,
    int wm, int wn, wmma::fragment<wmma::accumulator, 16, 16, 16, float> acc[4][2])
{
#pragma unroll
    for (int ks = 0; ks < 2; ks++) {
        wmma::fragment<wmma::matrix_a, 16, 16, 16, __nv_bfloat16, wmma::row_major> fah[4], fal[4];
#pragma unroll
        for (int i = 0; i < 4; i++) {
            wmma::load_matrix_sync(fah[i], sAH + (wm * 64 + i * 16) * LDT + ks * 16, LDT);
            wmma::load_matrix_sync(fal[i], sAL + (wm * 64 + i * 16) * LDT + ks * 16, LDT);
        }
#pragma unroll
        for (int j = 0; j < 2; j++) {
            wmma::fragment<wmma::matrix_b, 16, 16, 16, __nv_bfloat16, wmma::col_major> fbh, fbl;
            wmma::load_matrix_sync(fbh, sBH + (wn * 32 + j * 16) * LDT + ks * 16, LDT);
            wmma::load_matrix_sync(fbl, sBL + (wn * 32 + j * 16) * LDT + ks * 16, LDT);
#pragma unroll
            for (int i = 0; i < 4; i++) {
                wmma::mma_sync(acc[i][j], fah[i], fbh, acc[i][j]);
                wmma::mma_sync(acc[i][j], fah[i], fbl, acc[i][j]);
                wmma::mma_sync(acc[i][j], fal[i], fbh, acc[i][j]);
            }
        }
    }
}

// ================= fused dual-attend GEMM (round-9 winner, unchanged) =================
// grid (4, BA/128). bx 0,1: C0 = att.Wa2a^T -> tanh/Wd epilogue -> g_spart.
// bx 2,3: C1 = att.Wa2a1^T -> raw store to g_av1 (ld 256).
__global__ void __launch_bounds__(256) attend_dual(
    const float* __restrict__ att,
    const __nv_bfloat16* __restrict__ W0h, const __nv_bfloat16* __restrict__ W0l,
    const __nv_bfloat16* __restrict__ W1h, const __nv_bfloat16* __restrict__ W1l,
    const float* __restrict__ ba0, const float* __restrict__ Wd0)
{
    extern __shared__ char smem[];
    __nv_bfloat16* sAH = (__nv_bfloat16*)smem + OFF_AH;
    __nv_bfloat16* sAL = (__nv_bfloat16*)smem + OFF_AL;

    const int tid = threadIdx.x;
    const int wid = tid >> 5;
    const int wm = wid >> 2, wn = wid & 3;
    const int bx = blockIdx.x;
    const int m0 = blockIdx.y * 128;
    const bool second = (bx >= 2);
    const int n0 = (bx & 1) * 128;
    const __nv_bfloat16* Bh = second ? W1h : W0h;
    const __nv_bfloat16* Bl = second ? W1l : W0l;

    wmma::fragment<wmma::accumulator, 16, 16, 16, float> acc[4][2];
#pragma unroll
    for (int i = 0; i < 4; i++)
#pragma unroll
        for (int j = 0; j < 2; j++) wmma::fill_fragment(acc[i][j], 0.0f);

    const int r  = tid >> 1;
    const int ch = (tid & 1) * 16;
    const int Brow = n0 + r;
    const bool bvalid = (Brow < A_);
    const int BrowC = bvalid ? Brow : 0;
    const int psz = bvalid ? 16 : 0;

    const uint32_t sbase = smem_u32(smem);
    const uint32_t rowoff = (uint32_t)(r * LDT + ch) * 2;
    const uint32_t dBH[2] = { sbase + OFF_B0H * 2 + rowoff, sbase + OFF_B1H * 2 + rowoff };
    const uint32_t dBL[2] = { sbase + OFF_B0L * 2 + rowoff, sbase + OFF_B1L * 2 + rowoff };

    // prologue: B chunk 0 -> buf 0
    {
        const __nv_bfloat16* ph = Bh + (size_t)BrowC * 512 + ch;
        const __nv_bfloat16* pl = Bl + (size_t)BrowC * 512 + ch;
        cp16(dBH[0], ph, psz); cp16(dBH[0] + 16, ph + 8, psz);
        cp16(dBL[0], pl, psz); cp16(dBL[0] + 16, pl + 8, psz);
        cp_commit();
    }

    for (int kc = 0; kc < 16; kc++) {
        __syncthreads();   // prev MMA done: A buf + B[next] buf free
        // ---- A: fp32 -> split bf16 ----
        {
            __align__(16) float f[16];
            const float4* src = (const float4*)(att + (size_t)(m0 + r) * 512 + kc * 32 + ch);
            ((float4*)f)[0] = src[0]; ((float4*)f)[1] = src[1];
            ((float4*)f)[2] = src[2]; ((float4*)f)[3] = src[3];
            uint4 H[2], L[2];
            split16(f, H, L);
            *(uint4*)(sAH + r * LDT + ch)     = H[0];
            *(uint4*)(sAH + r * LDT + ch + 8) = H[1];
            *(uint4*)(sAL + r * LDT + ch)     = L[0];
            *(uint4*)(sAL + r * LDT + ch + 8) = L[1];
        }
        // ---- B: cp.async next chunk into other buffer ----
        if (kc < 15) {
            const int k0 = (kc + 1) * 32;
            const int buf = (kc + 1) & 1;
            const __nv_bfloat16* ph = Bh + (size_t)BrowC * 512 + k0 + ch;
            const __nv_bfloat16* pl = Bl + (size_t)BrowC * 512 + k0 + ch;
            cp16(dBH[buf], ph, psz); cp16(dBH[buf] + 16, ph + 8, psz);
            cp16(dBL[buf], pl, psz); cp16(dBL[buf] + 16, pl + 8, psz);
            cp_commit();
            cp_wait1();
        } else {
            cp_wait0();
        }
        __syncthreads();
        const __nv_bfloat16* sBH = (__nv_bfloat16*)smem + ((kc & 1) ? OFF_B1H : OFF_B0H);
        const __nv_bfloat16* sBL = (__nv_bfloat16*)smem + ((kc & 1) ? OFF_B1L : OFF_B0L);
        mma_tiles(sAH, sAL, sBH, sBL, wm, wn, acc);
    }

    if (second) {
        float* outz = g_av1 + (size_t)m0 * 256;
#pragma unroll
        for (int i = 0; i < 4; i++)
#pragma unroll
            for (int j = 0; j < 2; j++)
                wmma::store_matrix_sync(outz + (size_t)(wm * 64 + i * 16) * 256 + n0 + wn * 32 + j * 16,
                                        acc[i][j], 256, wmma::mem_row_major);
    } else {
        __syncthreads();
        float* Cs = (float*)smem;   // [128][132]
#pragma unroll
        for (int i = 0; i < 4; i++)
#pragma unroll
            for (int j = 0; j < 2; j++)
                wmma::store_matrix_sync(Cs + (wm * 64 + i * 16) * 132 + wn * 32 + j * 16,
                                        acc[i][j], 132, wmma::mem_row_major);
        __syncthreads();
        const int half = tid & 1;
        const int c0 = half * 64;
        float ahm = g_ah[m0 + r];
        float p = 0.f;
#pragma unroll 4
        for (int c = 0; c < 64; c++) {
            int o = n0 + c0 + c;
            if (o < A_)
                p += tanhf(Cs[r * 132 + c0 + c] + ba0[o] + ahm) * Wd0[o];
        }
        g_spart[(size_t)(m0 + r) * 4 + bx * 2 + half] = p;
    }
}

// ================= attend1 finish: scores from stored av1 =================
__global__ void attend1_score(const float* __restrict__ ba, const float* __restrict__ Wd,
                              const float* __restrict__ bd)
{
    const int w = (blockIdx.x * blockDim.x + threadIdx.x) >> 5;   // global warp = row
    const int lane = threadIdx.x & 31;
    if (w >= B_ * A_) return;
    const float* row = g_av1 + (size_t)w * 256;
    float ahm = g_ah[w];
    float p = 0.f;
#pragma unroll
    for (int it = 0; it < 7; it++) {
        int o = it * 32 + lane;
        if (o < A_) p += tanhf(row[o] + ba[o] + ahm) * Wd[o];
    }
#pragma unroll
    for (int off = 16; off > 0; off >>= 1)
        p += __shfl_down_sync(0xffffffff, p, off);
    if (lane == 0) g_score1[w] = p + bd[0];
}

// ================= gates / proj GEMM (round-9 winner, unchanged) =================
__global__ void __launch_bounds__(256, 2) tc_gemm(
    const float* __restrict__ A0, const float* __restrict__ A1, const float* __restrict__ A2,
    const __nv_bfloat16* __restrict__ Bh0, const __nv_bfloat16* __restrict__ Bl0,
    const __nv_bfloat16* __restrict__ Bh1, const __nv_bfloat16* __restrict__ Bl1,
    const __nv_bfloat16* __restrict__ Bh2, const __nv_bfloat16* __restrict__ Bl2,
    int Ntot, float* __restrict__ out, int ldout, size_t zstride)
{
    extern __shared__ char smem[];
    __nv_bfloat16* sAH = (__nv_bfloat16*)smem + OFF_AH;
    __nv_bfloat16* sAL = (__nv_bfloat16*)smem + OFF_AL;

    const int tid = threadIdx.x;
    const int wid = tid >> 5;
    const int wm = wid >> 2, wn = wid & 3;
    const int m0 = blockIdx.y * 128, n0 = blockIdx.x * 128;
    const int z = blockIdx.z;

    const float* Ap = (z == 0) ? A0 : (z == 1) ? A1 : A2;
    const __nv_bfloat16* Bh = (z == 0) ? Bh0 : (z == 1) ? Bh1 : Bh2;
    const __nv_bfloat16* Bl = (z == 0) ? Bl0 : (z == 1) ? Bl1 : Bl2;

    wmma::fragment<wmma::accumulator, 16, 16, 16, float> acc[4][2];
#pragma unroll
    for (int i = 0; i < 4; i++)
#pragma unroll
        for (int j = 0; j < 2; j++) wmma::fill_fragment(acc[i][j], 0.0f);

    const int r  = tid >> 1;
    const int ch = (tid & 1) * 16;
    const int Brow = n0 + r;
    const bool bvalid = (Brow < Ntot);
    const int BrowC = bvalid ? Brow : 0;
    const int psz = bvalid ? 16 : 0;

    const uint32_t sbase = smem_u32(smem);
    const uint32_t rowoff = (uint32_t)(r * LDT + ch) * 2;
    const uint32_t dBH[2] = { sbase + OFF_B0H * 2 + rowoff, sbase + OFF_B1H * 2 + rowoff };
    const uint32_t dBL[2] = { sbase + OFF_B0L * 2 + rowoff, sbase + OFF_B1L * 2 + rowoff };

    {
        const __nv_bfloat16* ph = Bh + (size_t)BrowC * 512 + ch;
        const __nv_bfloat16* pl = Bl + (size_t)BrowC * 512 + ch;
        cp16(dBH[0], ph, psz); cp16(dBH[0] + 16, ph + 8, psz);
        cp16(dBL[0], pl, psz); cp16(dBL[0] + 16, pl + 8, psz);
        cp_commit();
    }

    for (int kc = 0; kc < 16; kc++) {
        __syncthreads();
        {
            __align__(16) float f[16];
            const float4* src = (const float4*)(Ap + (size_t)(m0 + r) * 512 + kc * 32 + ch);
            ((float4*)f)[0] = src[0]; ((float4*)f)[1] = src[1];
            ((float4*)f)[2] = src[2]; ((float4*)f)[3] = src[3];
            uint4 H[2], L[2];
            split16(f, H, L);
            *(uint4*)(sAH + r * LDT + ch)     = H[0];
            *(uint4*)(sAH + r * LDT + ch + 8) = H[1];
            *(uint4*)(sAL + r * LDT + ch)     = L[0];
            *(uint4*)(sAL + r * LDT + ch + 8) = L[1];
        }
        if (kc < 15) {
            const int k0 = (kc + 1) * 32;
            const int buf = (kc + 1) & 1;
            const __nv_bfloat16* ph = Bh + (size_t)BrowC * 512 + k0 + ch;
            const __nv_bfloat16* pl = Bl + (size_t)BrowC * 512 + k0 + ch;
            cp16(dBH[buf], ph, psz); cp16(dBH[buf] + 16, ph + 8, psz);
            cp16(dBL[buf], pl, psz); cp16(dBL[buf] + 16, pl + 8, psz);
            cp_commit();
            cp_wait1();
        } else {
            cp_wait0();
        }
        __syncthreads();
        const __nv_bfloat16* sBH = (__nv_bfloat16*)smem + ((kc & 1) ? OFF_B1H : OFF_B0H);
        const __nv_bfloat16* sBL = (__nv_bfloat16*)smem + ((kc & 1) ? OFF_B1L : OFF_B0L);
        mma_tiles(sAH, sAL, sBH, sBL, wm, wn, acc);
    }

    float* outz = out + (size_t)z * zstride;
#pragma unroll
    for (int i = 0; i < 4; i++) {
        int mrow = m0 + wm * 64 + i * 16;
#pragma unroll
        for (int j = 0; j < 2; j++) {
            int ncol = n0 + wn * 32 + j * 16;
            if (ncol + 16 <= Ntot)
                wmma::store_matrix_sync(outz + (size_t)mrow * ldout + ncol, acc[i][j],
                                        ldout, wmma::mem_row_major);
        }
    }
}

// ================= fused conversion: all weights + gate bias in ONE launch =================
#define C_A2A   (A_ * R_ / 4)
#define C_BIG   (4 * R_ * R_ / 4)
#define C_PROJ  (V_ * R_ / 4)
#define SEG0 0
#define SEG1 (SEG0 + C_A2A)
#define SEG2 (SEG1 + C_A2A)
#define SEG3 (SEG2 + C_BIG)
#define SEG4 (SEG3 + C_BIG)
#define SEG5 (SEG4 + C_BIG)
#define SEG6 (SEG5 + C_PROJ)
#define SEG7 (SEG6 + (4 * R_ / 4))
#define CONV_BLOCKS (SEG7 / 256)

__device__ __forceinline__ void conv_one(const float* __restrict__ src,
                                         __nv_bfloat16* __restrict__ hi,
                                         __nv_bfloat16* __restrict__ lo, int i)
{
    float4 v = ((const float4*)src)[i];
    __nv_bfloat16 hx = __float2bfloat16_rn(v.x), hy = __float2bfloat16_rn(v.y);
    __nv_bfloat16 hz = __float2bfloat16_rn(v.z), hw = __float2bfloat16_rn(v.w);
    __nv_bfloat16 lx = __float2bfloat16_rn(v.x - __bfloat162float(hx));
    __nv_bfloat16 ly = __float2bfloat16_rn(v.y - __bfloat162float(hy));
    __nv_bfloat16 lz = __float2bfloat16_rn(v.z - __bfloat162float(hz));
    __nv_bfloat16 lw = __float2bfloat16_rn(v.w - __bfloat162float(hw));
    uint2 H, L;
    H.x = (uint32_t)__bfloat16_as_ushort(hx) | ((uint32_t)__bfloat16_as_ushort(hy) << 16);
    H.y = (uint32_t)__bfloat16_as_ushort(hz) | ((uint32_t)__bfloat16_as_ushort(hw) << 16);
    L.x = (uint32_t)__bfloat16_as_ushort(lx) | ((uint32_t)__bfloat16_as_ushort(ly) << 16);
    L.y = (uint32_t)__bfloat16_as_ushort(lz) | ((uint32_t)__bfloat16_as_ushort(lw) << 16);
    ((uint2*)hi)[i] = H;
    ((uint2*)lo)[i] = L;
}

__global__ void conv_all(
    const float* __restrict__ W_a2a, const float* __restrict__ W_a2a1,
    const float* __restrict__ W_i2h, const float* __restrict__ W_h2h,
    const float* __restrict__ W_a2h, const float* __restrict__ W_proj,
    const float* __restrict__ b1, const float* __restrict__ b2, const float* __restrict__ b3)
{
    int i = blockIdx.x * 256 + threadIdx.x;
    if (i < SEG1)      conv_one(W_a2a,  g_Wa2a_h,  g_Wa2a_l,  i - SEG0);
    else if (i < SEG2) conv_one(W_a2a1, g_Wa2a1_h, g_Wa2a1_l, i - SEG1);
    else if (i < SEG3) conv_one(W_i2h,  g_Wi_h,    g_Wi_l,    i - SEG2);
    else if (i < SEG4) conv_one(W_h2h,  g_Wh_h,    g_Wh_l,    i - SEG3);
    else if (i < SEG5) conv_one(W_a2h,  g_Wah_h,   g_Wah_l,   i - SEG4);
    else if (i < SEG6) conv_one(W_proj, g_Wp_h,    g_Wp_l,    i - SEG5);
    else if (i < SEG7) {
        int k = i - SEG6;
        float4 v1 = ((const float4*)b1)[k];
        float4 v2 = ((const float4*)b2)[k];
        float4 v3 = ((const float4*)b3)[k];
        float4 o;
        o.x = v1.x + v2.x + v3.x; o.y = v1.y + v2.y + v3.y;
        o.z = v1.z + v2.z + v3.z; o.w = v1.w + v2.w + v3.w;
        ((float4*)g_bias)[k] = o;
    }
}

// ================= SIMT sgemm for the small ah projection =================
__global__ void __launch_bounds__(256, 2) sgemm_bias(
    const float* __restrict__ Am, const float* __restrict__ Bm,
    const float* __restrict__ b1,
    float* __restrict__ C, int M, int N, int K)
{
    __shared__ __align__(16) float As[16][68];
    __shared__ __align__(16) float Bs[16][68];
    const int m0 = blockIdx.y * 64, n0 = blockIdx.x * 64;
    const int tid = threadIdx.x;
    const int tn = tid & 15, tm = tid >> 4;
    const int lrow = tid >> 2, lc = (tid & 3) << 2;

    float acc[4][4] = {};
    for (int k0 = 0; k0 < K; k0 += 16) {
        float4 av = make_float4(0.f, 0.f, 0.f, 0.f);
        float4 bv = make_float4(0.f, 0.f, 0.f, 0.f);
        if (m0 + lrow < M) av = *(const float4*)(Am + (size_t)(m0 + lrow) * K + k0 + lc);
        if (n0 + lrow < N) bv = *(const float4*)(Bm + (size_t)(n0 + lrow) * K + k0 + lc);
        __syncthreads();
        As[lc + 0][lrow] = av.x; As[lc + 1][lrow] = av.y; As[lc + 2][lrow] = av.z; As[lc + 3][lrow] = av.w;
        Bs[lc + 0][lrow] = bv.x; Bs[lc + 1][lrow] = bv.y; Bs[lc + 2][lrow] = bv.z; Bs[lc + 3][lrow] = bv.w;
        __syncthreads();
#pragma unroll
        for (int kk = 0; kk < 16; kk++) {
            float a[4], b[4];
            *(float4*)a = *(const float4*)&As[kk][tm << 2];
            *(float4*)b = *(const float4*)&Bs[kk][tn << 2];
#pragma unroll
            for (int i = 0; i < 4; i++)
#pragma unroll
                for (int j = 0; j < 4; j++)
                    acc[i][j] += a[i] * b[j];
        }
    }
#pragma unroll
    for (int j = 0; j < 4; j++) {
        int n = n0 + (tn << 2) + j;
        if (n >= N) continue;
        float bias = b1 ? b1[n] : 0.f;
#pragma unroll
        for (int i = 0; i < 4; i++) {
            int m = m0 + (tm << 2) + i;
            if (m < M) C[(size_t)m * N + n] = acc[i][j] + bias;
        }
    }
}

// ================= softmax over a -> g_w =================
// scores == nullptr -> from g_spart + bd ; else direct scores
__global__ void softmax_w(const float* __restrict__ bd, const float* __restrict__ scores)
{
    const int b = blockIdx.x, tid = threadIdx.x;  // 256 threads
    __shared__ float rbuf[256];

    float s = -1e30f;
    if (tid < A_) {
        if (scores) {
            s = scores[b * A_ + tid];
        } else {
            const float* p = &g_spart[(size_t)(b * A_ + tid) * 4];
            s = bd[0] + p[0] + p[1] + p[2] + p[3];
        }
    }
    rbuf[tid] = s;
    __syncthreads();
    for (int off = 128; off > 0; off >>= 1) {
        if (tid < off) rbuf[tid] = fmaxf(rbuf[tid], rbuf[tid + off]);
        __syncthreads();
    }
    float mx = rbuf[0];
    __syncthreads();
    float e = (tid < A_) ? __expf(s - mx) : 0.f;
    rbuf[tid] = e;
    __syncthreads();
    for (int off = 128; off > 0; off >>= 1) {
        if (tid < off) rbuf[tid] += rbuf[tid + off];
        __syncthreads();
    }
    float inv = 1.f / rbuf[0];
    if (tid < A_) g_w[b * A_ + tid] = e * inv;
}

// ================= weighted sum: grid (B, 4), 128 threads =================
// blockIdx.y selects R-quarter (32 float4 cols). Threads: 32 cols x 4 a-quarters.
__global__ void __launch_bounds__(128) attend_wsum(const float* __restrict__ att,
                                                   float* __restrict__ outres)
{
    const int b = blockIdx.x, q = blockIdx.y;
    const int tid = threadIdx.x;
    const int col = tid & 31, aq = tid >> 5;     // a-quarter 0..3 (49 each; 4*49=196)
    __shared__ float w[A_];
    __shared__ __align__(16) float4 part[3][32];

    for (int i = tid; i < A_; i += 128) w[i] = g_w[b * A_ + i];
    __syncthreads();

    const float* ab = att + (size_t)b * A_ * R_ + q * 128 + col * 4;
    float4 acc = make_float4(0.f, 0.f, 0.f, 0.f);
    const int a0 = aq * 49, a1 = a0 + 49;
#pragma unroll 7
    for (int a = a0; a < a1; a++) {
        float4 v = *(const float4*)(ab + (size_t)a * R_);
        float wa = w[a];
        acc.x += v.x * wa; acc.y += v.y * wa;
        acc.z += v.z * wa; acc.w += v.w * wa;
    }
    if (aq > 0) part[aq - 1][col] = acc;
    __syncthreads();
    if (aq == 0) {
#pragma unroll
        for (int p = 0; p < 3; p++) {
            float4 v = part[p][col];
            acc.x += v.x; acc.y += v.y; acc.z += v.z; acc.w += v.w;
        }
        *(float4*)(outres + (size_t)b * R_ + q * 128 + col * 4) = acc;
    }
}

// ================= LSTM cell (float4, sums 3 phase slabs + bias) =================
__global__ void lstm_cell(const float* __restrict__ prev_c, float* __restrict__ out_c)
{
    int idx = blockIdx.x * 256 + threadIdx.x;     // over B*R/4
    if (idx >= B_ * R_ / 4) return;
    int b = idx >> 7;                  // R_/4 = 128
    int j4 = (idx & 127) * 4;
    const size_t base = (size_t)b * 4 * R_;

    float4 sv[4];
#pragma unroll
    for (int g = 0; g < 4; g++) {
        size_t o = base + g * R_ + j4;
        float4 v0 = *(const float4*)&g_sums[0][o];
        float4 v1 = *(const float4*)&g_sums[1][o];
        float4 v2 = *(const float4*)&g_sums[2][o];
        float4 bb = *(const float4*)&g_bias[g * R_ + j4];
        sv[g].x = v0.x + v1.x + v2.x + bb.x;
        sv[g].y = v0.y + v1.y + v2.y + bb.y;
        sv[g].z = v0.z + v1.z + v2.z + bb.z;
        sv[g].w = v0.w + v1.w + v2.w + bb.w;
    }
    float4 pc = *(const float4*)(prev_c + (size_t)b * R_ + j4);
    float4 oc, oh;
#pragma unroll
    for (int e = 0; e < 4; e++) {
        float s0 = (&sv[0].x)[e], s1 = (&sv[1].x)[e], s2 = (&sv[2].x)[e], s3 = (&sv[3].x)[e];
        float ig = 1.f / (1.f + __expf(-s0));
        float fg = 1.f / (1.f + __expf(-s1));
        float og = 1.f / (1.f + __expf(-s2));
        float gt = tanhf(s3);
        float c = fg * (&pc.x)[e] + ig * gt;
        (&oc.x)[e] = c;
        (&oh.x)[e] = og * tanhf(c);
    }
    *(float4*)(out_c + (size_t)b * R_ + j4) = oc;
    *(float4*)(g_nexth + (size_t)b * R_ + j4) = oh;
}

__global__ void add_toph(float* __restrict__ out_h)
{
    int idx = blockIdx.x * 256 + threadIdx.x;
    if (idx >= B_ * R_) return;
    out_h[idx] = g_attres[idx] + g_nexth[idx];
}

// ================= log_softmax: online (max,sum) pass + write pass =================
__global__ void log_softmax_kernel(float* __restrict__ logits, const float* __restrict__ bias)
{
    const int b = blockIdx.x, tid = threadIdx.x;  // 512 threads
    float* row = logits + (size_t)b * V_;
    __shared__ float rm[512], rd[512];

    float m = -1e30f, d = 0.f;
    for (int i = tid; i < V_; i += 512) {
        float v = row[i] + bias[i];
        if (v > m) { d = d * __expf(m - v) + 1.f; m = v; }
        else d += __expf(v - m);
    }
    rm[tid] = m; rd[tid] = d;
    __syncthreads();
    for (int off = 256; off > 0; off >>= 1) {
        if (tid < off) {
            float m2 = rm[tid + off], d2 = rd[tid + off];
            float mo = fmaxf(rm[tid], m2);
            rd[tid] = rd[tid] * __expf(rm[tid] - mo) + d2 * __expf(m2 - mo);
            rm[tid] = mo;
        }
        __syncthreads();
    }
    float lse = rm[0] + logf(rd[0]);
    for (int i = tid; i < V_; i += 512) row[i] = row[i] + bias[i] - lse;
}

// ================= host launch =================
extern "C" void kernel_launch(void* const* d_in, const int* in_sizes, int n_in,
                              void* d_out, int out_size)
{
    const float* x      = (const float*)d_in[0];
    const float* att    = (const float*)d_in[1];
    const float* prev_c = (const float*)d_in[2];
    const float* prev_h = (const float*)d_in[3];
    const float* W_a2a  = (const float*)d_in[4];  const float* b_a2a  = (const float*)d_in[5];
    const float* W_h2a  = (const float*)d_in[6];  const float* b_h2a  = (const float*)d_in[7];
    const float* W_d2d  = (const float*)d_in[8];  const float* b_d2d  = (const float*)d_in[9];
    const float* W_i2h  = (const float*)d_in[10]; const float* b_i2h  = (const float*)d_in[11];
    const float* W_a2h  = (const float*)d_in[12]; const float* b_a2h  = (const float*)d_in[13];
    const float* W_h2h  = (const float*)d_in[14]; const float* b_h2h  = (const float*)d_in[15];
    const float* W_a2a1 = (const float*)d_in[16]; const float* b_a2a1 = (const float*)d_in[17];
    const float* W_h2a1 = (const float*)d_in[18]; const float* b_h2a1 = (const float*)d_in[19];
    const float* W_d2d1 = (const float*)d_in[20]; const float* b_d2d1 = (const float*)d_in[21];
    const float* W_proj = (const float*)d_in[22]; const float* b_proj = (const float*)d_in[23];

    float* out   = (float*)d_out;
    float* out_c = out;                  // next_c  [B,R]
    float* out_h = out + B_ * R_;        // top_h   [B,R]
    float* out_l = out + 2 * B_ * R_;    // logsoft [B,V]

    float *ah_p, *attres_p, *nexth_p, *sums_p, *score1_p;
    cudaGetSymbolAddress((void**)&ah_p,     g_ah);
    cudaGetSymbolAddress((void**)&attres_p, g_attres);
    cudaGetSymbolAddress((void**)&nexth_p,  g_nexth);
    cudaGetSymbolAddress((void**)&sums_p,   g_sums);
    cudaGetSymbolAddress((void**)&score1_p, g_score1);

    __nv_bfloat16 *Wa2a_h, *Wa2a_l, *Wa2a1_h, *Wa2a1_l, *Wi_h, *Wi_l, *Wh_h, *Wh_l, *Wah_h, *Wah_l, *Wp_h, *Wp_l;
    cudaGetSymbolAddress((void**)&Wa2a_h,  g_Wa2a_h);  cudaGetSymbolAddress((void**)&Wa2a_l,  g_Wa2a_l);
    cudaGetSymbolAddress((void**)&Wa2a1_h, g_Wa2a1_h); cudaGetSymbolAddress((void**)&Wa2a1_l, g_Wa2a1_l);
    cudaGetSymbolAddress((void**)&Wi_h,    g_Wi_h);    cudaGetSymbolAddress((void**)&Wi_l,    g_Wi_l);
    cudaGetSymbolAddress((void**)&Wh_h,    g_Wh_h);    cudaGetSymbolAddress((void**)&Wh_l,    g_Wh_l);
    cudaGetSymbolAddress((void**)&Wah_h,   g_Wah_h);   cudaGetSymbolAddress((void**)&Wah_l,   g_Wah_l);
    cudaGetSymbolAddress((void**)&Wp_h,    g_Wp_h);    cudaGetSymbolAddress((void**)&Wp_l,    g_Wp_l);

    cudaFuncSetAttribute(attend_dual, cudaFuncAttributeMaxDynamicSharedMemorySize, SMEM_DUAL);
    cudaFuncSetAttribute(tc_gemm,     cudaFuncAttributeMaxDynamicSharedMemorySize, SMEM_GEMM);

    const dim3 blk(256);

    // ---- all weight conversions + gate bias in one launch ----
    conv_all<<<CONV_BLOCKS, blk>>>(W_a2a, W_a2a1, W_i2h, W_h2h, W_a2h, W_proj,
                                   b_i2h, b_h2h, b_a2h);

    // ---- ah0 + fused dual attend GEMM ----
    sgemm_bias<<<dim3((A_ + 63) / 64, (B_ + 63) / 64), blk>>>(prev_h, W_h2a, b_h2a, ah_p, B_, A_, R_);
    attend_dual<<<dim3(4, (B_ * A_) / 128), blk, SMEM_DUAL>>>(
        att, Wa2a_h, Wa2a_l, Wa2a1_h, Wa2a1_l, b_a2a, W_d2d);
    softmax_w<<<B_, blk>>>(b_d2d, nullptr);
    attend_wsum<<<dim3(B_, 4), 128>>>(att, attres_p);

    // ---- LSTM gates (3 phases in grid.z) + cell ----
    tc_gemm<<<dim3(16, 2, 3), blk, SMEM_GEMM>>>(
        x, prev_h, attres_p,
        Wi_h, Wi_l, Wh_h, Wh_l, Wah_h, Wah_l,
        4 * R_, sums_p, 4 * R_, (size_t)B_ * 4 * R_);
    lstm_cell<<<(B_ * R_ / 4 + 255) / 256, blk>>>(prev_c, out_c);

    // ---- attend #1 finish (cheap) ----
    sgemm_bias<<<dim3((A_ + 63) / 64, (B_ + 63) / 64), blk>>>(nexth_p, W_h2a1, b_h2a1, ah_p, B_, A_, R_);
    attend1_score<<<(B_ * A_ * 32 + 255) / 256, blk>>>(b_a2a1, W_d2d1, b_d2d1);
    softmax_w<<<B_, blk>>>(nullptr, score1_p);
    attend_wsum<<<dim3(B_, 4), 128>>>(att, attres_p);

    // ---- top_h, projection, log_softmax ----
    add_toph<<<(B_ * R_ + 255) / 256, blk>>>(out_h);
    tc_gemm<<<dim3((V_ + 127) / 128, 2, 1), blk, SMEM_GEMM>>>(
        out_h, nullptr, nullptr,
        Wp_h, Wp_l, nullptr, nullptr, nullptr, nullptr,
        V_, out_l, V_, 0);
    log_softmax_kernel<<<B_, 512>>>(out_l, b_proj);
}

// round 14
// speedup vs baseline: 1.4563x; 1.4563x over previous
#include <cuda_runtime.h>
#include <cuda_bf16.h>
#include <mma.h>
#include <cstdint>

using namespace nvcuda;

#define B_ 256
#define I_ 512
#define R_ 512
#define A_ 196
#define V_ 10000

// ================= scratch (static device; no allocation allowed) =================
__device__ float g_ah[B_ * A_];            // [B, A]
__device__ float g_spart[B_ * A_ * 4];     // attend0 score partials (2 nblocks x 2 halves)
__device__ float g_score1[B_ * A_];        // attend1 scores
__device__ float g_av1[B_ * A_ * 256];     // raw att.Wa2a1^T (padded N=256), 51.4MB
__device__ float g_attres[B_ * R_];        // [B, R]
__device__ float g_sums[3][B_ * 4 * R_];   // per-phase gate GEMM results
__device__ float g_nexth[B_ * R_];         // [B, R]
__device__ float g_bias[4 * R_];           // combined gate bias

// split-bf16 weight caches
__device__ __nv_bfloat16 g_Wa2a_h[A_ * R_],  g_Wa2a_l[A_ * R_];
__device__ __nv_bfloat16 g_Wa2a1_h[A_ * R_], g_Wa2a1_l[A_ * R_];
__device__ __nv_bfloat16 g_Wi_h[4 * R_ * I_], g_Wi_l[4 * R_ * I_];
__device__ __nv_bfloat16 g_Wh_h[4 * R_ * R_], g_Wh_l[4 * R_ * R_];
__device__ __nv_bfloat16 g_Wah_h[4 * R_ * R_], g_Wah_l[4 * R_ * R_];
__device__ __nv_bfloat16 g_Wp_h[V_ * R_], g_Wp_l[V_ * R_];

// smem staging (bf16 elems, ld = 40); tile = 128x32 = 5120 elems
// A single-buffered, B double-buffered (cp.async)
#define LDT 40
#define OFF_AH  0
#define OFF_AL  5120
#define OFF_B0H 10240
#define OFF_B0L 15360
#define OFF_B1H 20480
#define OFF_B1L 25600
#define SMEM_GEMM 61440
#define SMEM_DUAL 69632   // max(staging 61440, 128x132 fp32 C tile 67584)

// pack 16 floats -> 2x uint4 hi + 2x uint4 lo (8 bf16 per uint4)
__device__ __forceinline__ void split16(const float* f, uint4* H, uint4* L) {
    __align__(16) unsigned short hs[16];
    __align__(16) unsigned short ls[16];
#pragma unroll
    for (int e = 0; e < 16; e++) {
        __nv_bfloat16 h = __float2bfloat16_rn(f[e]);
        hs[e] = __bfloat16_as_ushort(h);
        ls[e] = __bfloat16_as_ushort(__float2bfloat16_rn(f[e] - __bfloat162float(h)));
    }
    H[0] = ((uint4*)hs)[0]; H[1] = ((uint4*)hs)[1];
    L[0] = ((uint4*)ls)[0]; L[1] = ((uint4*)ls)[1];
}

__device__ __forceinline__ uint32_t smem_u32(const void* p) {
    uint32_t a;
    asm("{ .reg .u64 t; cvta.to.shared.u64 t, %1; cvt.u32.u64 %0, t; }" : "=r"(a) : "l"(p));
    return a;
}
// cp.async 16B with zero-fill when src_sz == 0
__device__ __forceinline__ void cp16(uint32_t dst, const void* src, int src_sz) {
    asm volatile("cp.async.cg.shared.global [%0], [%1], 16, %2;"
                 :: "r"(dst), "l"(src), "r"(src_sz));
}
__device__ __forceinline__ void cp_commit() { asm volatile("cp.async.commit_group;"); }
__device__ __forceinline__ void cp_wait1() { asm volatile("cp.async.wait_group 1;"); }
__device__ __forceinline__ void cp_wait0() { asm volatile("cp.async.wait_group 0;"); }

// ---- shared MMA inner step over staged tiles ----
__device__ __forceinline__ void mma_tiles(
    const __nv_bfloat16* sAH, const __nv_bfloat16* sAL,
    const __nv_bfloat16* sBH, const __nv_bfloat16* sBL,
    int wm, int wn, wmma::fragment<wmma::accumulator, 16, 16, 16, float> acc[4][2])
{
#pragma unroll
    for (int ks = 0; ks < 2; ks++) {
        wmma::fragment<wmma::matrix_a, 16, 16, 16, __nv_bfloat16, wmma::row_major> fah[4], fal[4];
#pragma unroll
        for (int i = 0; i < 4; i++) {
            wmma::load_matrix_sync(fah[i], sAH + (wm * 64 + i * 16) * LDT + ks * 16, LDT);
            wmma::load_matrix_sync(fal[i], sAL + (wm * 64 + i * 16) * LDT + ks * 16, LDT);
        }
#pragma unroll
        for (int j = 0; j < 2; j++) {
            wmma::fragment<wmma::matrix_b, 16, 16, 16, __nv_bfloat16, wmma::col_major> fbh, fbl;
            wmma::load_matrix_sync(fbh, sBH + (wn * 32 + j * 16) * LDT + ks * 16, LDT);
            wmma::load_matrix_sync(fbl, sBL + (wn * 32 + j * 16) * LDT + ks * 16, LDT);
#pragma unroll
            for (int i = 0; i < 4; i++) {
                wmma::mma_sync(acc[i][j], fah[i], fbh, acc[i][j]);
                wmma::mma_sync(acc[i][j], fah[i], fbl, acc[i][j]);
                wmma::mma_sync(acc[i][j], fal[i], fbh, acc[i][j]);
            }
        }
    }
}

// ================= fused dual-attend GEMM (round-9 winner, unchanged) =================
// grid (4, BA/128). bx 0,1: C0 = att.Wa2a^T -> tanh/Wd epilogue -> g_spart.
// bx 2,3: C1 = att.Wa2a1^T -> raw store to g_av1 (ld 256).
__global__ void __launch_bounds__(256) attend_dual(
    const float* __restrict__ att,
    const __nv_bfloat16* __restrict__ W0h, const __nv_bfloat16* __restrict__ W0l,
    const __nv_bfloat16* __restrict__ W1h, const __nv_bfloat16* __restrict__ W1l,
    const float* __restrict__ ba0, const float* __restrict__ Wd0)
{
    extern __shared__ char smem[];
    __nv_bfloat16* sAH = (__nv_bfloat16*)smem + OFF_AH;
    __nv_bfloat16* sAL = (__nv_bfloat16*)smem + OFF_AL;

    const int tid = threadIdx.x;
    const int wid = tid >> 5;
    const int wm = wid >> 2, wn = wid & 3;
    const int bx = blockIdx.x;
    const int m0 = blockIdx.y * 128;
    const bool second = (bx >= 2);
    const int n0 = (bx & 1) * 128;
    const __nv_bfloat16* Bh = second ? W1h : W0h;
    const __nv_bfloat16* Bl = second ? W1l : W0l;

    wmma::fragment<wmma::accumulator, 16, 16, 16, float> acc[4][2];
#pragma unroll
    for (int i = 0; i < 4; i++)
#pragma unroll
        for (int j = 0; j < 2; j++) wmma::fill_fragment(acc[i][j], 0.0f);

    const int r  = tid >> 1;
    const int ch = (tid & 1) * 16;
    const int Brow = n0 + r;
    const bool bvalid = (Brow < A_);
    const int BrowC = bvalid ? Brow : 0;
    const int psz = bvalid ? 16 : 0;

    const uint32_t sbase = smem_u32(smem);
    const uint32_t rowoff = (uint32_t)(r * LDT + ch) * 2;
    const uint32_t dBH[2] = { sbase + OFF_B0H * 2 + rowoff, sbase + OFF_B1H * 2 + rowoff };
    const uint32_t dBL[2] = { sbase + OFF_B0L * 2 + rowoff, sbase + OFF_B1L * 2 + rowoff };

    // prologue: B chunk 0 -> buf 0
    {
        const __nv_bfloat16* ph = Bh + (size_t)BrowC * 512 + ch;
        const __nv_bfloat16* pl = Bl + (size_t)BrowC * 512 + ch;
        cp16(dBH[0], ph, psz); cp16(dBH[0] + 16, ph + 8, psz);
        cp16(dBL[0], pl, psz); cp16(dBL[0] + 16, pl + 8, psz);
        cp_commit();
    }

    for (int kc = 0; kc < 16; kc++) {
        __syncthreads();   // prev MMA done: A buf + B[next] buf free
        // ---- A: fp32 -> split bf16 ----
        {
            __align__(16) float f[16];
            const float4* src = (const float4*)(att + (size_t)(m0 + r) * 512 + kc * 32 + ch);
            ((float4*)f)[0] = src[0]; ((float4*)f)[1] = src[1];
            ((float4*)f)[2] = src[2]; ((float4*)f)[3] = src[3];
            uint4 H[2], L[2];
            split16(f, H, L);
            *(uint4*)(sAH + r * LDT + ch)     = H[0];
            *(uint4*)(sAH + r * LDT + ch + 8) = H[1];
            *(uint4*)(sAL + r * LDT + ch)     = L[0];
            *(uint4*)(sAL + r * LDT + ch + 8) = L[1];
        }
        // ---- B: cp.async next chunk into other buffer ----
        if (kc < 15) {
            const int k0 = (kc + 1) * 32;
            const int buf = (kc + 1) & 1;
            const __nv_bfloat16* ph = Bh + (size_t)BrowC * 512 + k0 + ch;
            const __nv_bfloat16* pl = Bl + (size_t)BrowC * 512 + k0 + ch;
            cp16(dBH[buf], ph, psz); cp16(dBH[buf] + 16, ph + 8, psz);
            cp16(dBL[buf], pl, psz); cp16(dBL[buf] + 16, pl + 8, psz);
            cp_commit();
            cp_wait1();
        } else {
            cp_wait0();
        }
        __syncthreads();
        const __nv_bfloat16* sBH = (__nv_bfloat16*)smem + ((kc & 1) ? OFF_B1H : OFF_B0H);
        const __nv_bfloat16* sBL = (__nv_bfloat16*)smem + ((kc & 1) ? OFF_B1L : OFF_B0L);
        mma_tiles(sAH, sAL, sBH, sBL, wm, wn, acc);
    }

    if (second) {
        float* outz = g_av1 + (size_t)m0 * 256;
#pragma unroll
        for (int i = 0; i < 4; i++)
#pragma unroll
            for (int j = 0; j < 2; j++)
                wmma::store_matrix_sync(outz + (size_t)(wm * 64 + i * 16) * 256 + n0 + wn * 32 + j * 16,
                                        acc[i][j], 256, wmma::mem_row_major);
    } else {
        __syncthreads();
        float* Cs = (float*)smem;   // [128][132]
#pragma unroll
        for (int i = 0; i < 4; i++)
#pragma unroll
            for (int j = 0; j < 2; j++)
                wmma::store_matrix_sync(Cs + (wm * 64 + i * 16) * 132 + wn * 32 + j * 16,
                                        acc[i][j], 132, wmma::mem_row_major);
        __syncthreads();
        const int half = tid & 1;
        const int c0 = half * 64;
        float ahm = g_ah[m0 + r];
        float p = 0.f;
#pragma unroll 4
        for (int c = 0; c < 64; c++) {
            int o = n0 + c0 + c;
            if (o < A_)
                p += tanhf(Cs[r * 132 + c0 + c] + ba0[o] + ahm) * Wd0[o];
        }
        g_spart[(size_t)(m0 + r) * 4 + bx * 2 + half] = p;
    }
}

// ================= attend1 finish: scores from stored av1 =================
__global__ void attend1_score(const float* __restrict__ ba, const float* __restrict__ Wd,
                              const float* __restrict__ bd)
{
    const int w = (blockIdx.x * blockDim.x + threadIdx.x) >> 5;   // global warp = row
    const int lane = threadIdx.x & 31;
    if (w >= B_ * A_) return;
    const float* row = g_av1 + (size_t)w * 256;
    float ahm = g_ah[w];
    float p = 0.f;
#pragma unroll
    for (int it = 0; it < 7; it++) {
        int o = it * 32 + lane;
        if (o < A_) p += tanhf(row[o] + ba[o] + ahm) * Wd[o];
    }
#pragma unroll
    for (int off = 16; off > 0; off >>= 1)
        p += __shfl_down_sync(0xffffffff, p, off);
    if (lane == 0) g_score1[w] = p + bd[0];
}

// ================= gates / proj GEMM (round-9 winner, unchanged) =================
__global__ void __launch_bounds__(256, 2) tc_gemm(
    const float* __restrict__ A0, const float* __restrict__ A1, const float* __restrict__ A2,
    const __nv_bfloat16* __restrict__ Bh0, const __nv_bfloat16* __restrict__ Bl0,
    const __nv_bfloat16* __restrict__ Bh1, const __nv_bfloat16* __restrict__ Bl1,
    const __nv_bfloat16* __restrict__ Bh2, const __nv_bfloat16* __restrict__ Bl2,
    int Ntot, float* __restrict__ out, int ldout, size_t zstride)
{
    extern __shared__ char smem[];
    __nv_bfloat16* sAH = (__nv_bfloat16*)smem + OFF_AH;
    __nv_bfloat16* sAL = (__nv_bfloat16*)smem + OFF_AL;

    const int tid = threadIdx.x;
    const int wid = tid >> 5;
    const int wm = wid >> 2, wn = wid & 3;
    const int m0 = blockIdx.y * 128, n0 = blockIdx.x * 128;
    const int z = blockIdx.z;

    const float* Ap = (z == 0) ? A0 : (z == 1) ? A1 : A2;
    const __nv_bfloat16* Bh = (z == 0) ? Bh0 : (z == 1) ? Bh1 : Bh2;
    const __nv_bfloat16* Bl = (z == 0) ? Bl0 : (z == 1) ? Bl1 : Bl2;

    wmma::fragment<wmma::accumulator, 16, 16, 16, float> acc[4][2];
#pragma unroll
    for (int i = 0; i < 4; i++)
#pragma unroll
        for (int j = 0; j < 2; j++) wmma::fill_fragment(acc[i][j], 0.0f);

    const int r  = tid >> 1;
    const int ch = (tid & 1) * 16;
    const int Brow = n0 + r;
    const bool bvalid = (Brow < Ntot);
    const int BrowC = bvalid ? Brow : 0;
    const int psz = bvalid ? 16 : 0;

    const uint32_t sbase = smem_u32(smem);
    const uint32_t rowoff = (uint32_t)(r * LDT + ch) * 2;
    const uint32_t dBH[2] = { sbase + OFF_B0H * 2 + rowoff, sbase + OFF_B1H * 2 + rowoff };
    const uint32_t dBL[2] = { sbase + OFF_B0L * 2 + rowoff, sbase + OFF_B1L * 2 + rowoff };

    {
        const __nv_bfloat16* ph = Bh + (size_t)BrowC * 512 + ch;
        const __nv_bfloat16* pl = Bl + (size_t)BrowC * 512 + ch;
        cp16(dBH[0], ph, psz); cp16(dBH[0] + 16, ph + 8, psz);
        cp16(dBL[0], pl, psz); cp16(dBL[0] + 16, pl + 8, psz);
        cp_commit();
    }

    for (int kc = 0; kc < 16; kc++) {
        __syncthreads();
        {
            __align__(16) float f[16];
            const float4* src = (const float4*)(Ap + (size_t)(m0 + r) * 512 + kc * 32 + ch);
            ((float4*)f)[0] = src[0]; ((float4*)f)[1] = src[1];
            ((float4*)f)[2] = src[2]; ((float4*)f)[3] = src[3];
            uint4 H[2], L[2];
            split16(f, H, L);
            *(uint4*)(sAH + r * LDT + ch)     = H[0];
            *(uint4*)(sAH + r * LDT + ch + 8) = H[1];
            *(uint4*)(sAL + r * LDT + ch)     = L[0];
            *(uint4*)(sAL + r * LDT + ch + 8) = L[1];
        }
        if (kc < 15) {
            const int k0 = (kc + 1) * 32;
            const int buf = (kc + 1) & 1;
            const __nv_bfloat16* ph = Bh + (size_t)BrowC * 512 + k0 + ch;
            const __nv_bfloat16* pl = Bl + (size_t)BrowC * 512 + k0 + ch;
            cp16(dBH[buf], ph, psz); cp16(dBH[buf] + 16, ph + 8, psz);
            cp16(dBL[buf], pl, psz); cp16(dBL[buf] + 16, pl + 8, psz);
            cp_commit();
            cp_wait1();
        } else {
            cp_wait0();
        }
        __syncthreads();
        const __nv_bfloat16* sBH = (__nv_bfloat16*)smem + ((kc & 1) ? OFF_B1H : OFF_B0H);
        const __nv_bfloat16* sBL = (__nv_bfloat16*)smem + ((kc & 1) ? OFF_B1L : OFF_B0L);
        mma_tiles(sAH, sAL, sBH, sBL, wm, wn, acc);
    }

    float* outz = out + (size_t)z * zstride;
#pragma unroll
    for (int i = 0; i < 4; i++) {
        int mrow = m0 + wm * 64 + i * 16;
#pragma unroll
        for (int j = 0; j < 2; j++) {
            int ncol = n0 + wn * 32 + j * 16;
            if (ncol + 16 <= Ntot)
                wmma::store_matrix_sync(outz + (size_t)mrow * ldout + ncol, acc[i][j],
                                        ldout, wmma::mem_row_major);
        }
    }
}

// ================= fused conversion: all weights + gate bias in ONE launch =================
#define C_A2A   (A_ * R_ / 4)
#define C_BIG   (4 * R_ * R_ / 4)
#define C_PROJ  (V_ * R_ / 4)
#define SEG0 0
#define SEG1 (SEG0 + C_A2A)
#define SEG2 (SEG1 + C_A2A)
#define SEG3 (SEG2 + C_BIG)
#define SEG4 (SEG3 + C_BIG)
#define SEG5 (SEG4 + C_BIG)
#define SEG6 (SEG5 + C_PROJ)
#define SEG7 (SEG6 + (4 * R_ / 4))
#define CONV_BLOCKS (SEG7 / 256)

__device__ __forceinline__ void conv_one(const float* __restrict__ src,
                                         __nv_bfloat16* __restrict__ hi,
                                         __nv_bfloat16* __restrict__ lo, int i)
{
    float4 v = ((const float4*)src)[i];
    __nv_bfloat16 hx = __float2bfloat16_rn(v.x), hy = __float2bfloat16_rn(v.y);
    __nv_bfloat16 hz = __float2bfloat16_rn(v.z), hw = __float2bfloat16_rn(v.w);
    __nv_bfloat16 lx = __float2bfloat16_rn(v.x - __bfloat162float(hx));
    __nv_bfloat16 ly = __float2bfloat16_rn(v.y - __bfloat162float(hy));
    __nv_bfloat16 lz = __float2bfloat16_rn(v.z - __bfloat162float(hz));
    __nv_bfloat16 lw = __float2bfloat16_rn(v.w - __bfloat162float(hw));
    uint2 H, L;
    H.x = (uint32_t)__bfloat16_as_ushort(hx) | ((uint32_t)__bfloat16_as_ushort(hy) << 16);
    H.y = (uint32_t)__bfloat16_as_ushort(hz) | ((uint32_t)__bfloat16_as_ushort(hw) << 16);
    L.x = (uint32_t)__bfloat16_as_ushort(lx) | ((uint32_t)__bfloat16_as_ushort(ly) << 16);
    L.y = (uint32_t)__bfloat16_as_ushort(lz) | ((uint32_t)__bfloat16_as_ushort(lw) << 16);
    ((uint2*)hi)[i] = H;
    ((uint2*)lo)[i] = L;
}

__global__ void conv_all(
    const float* __restrict__ W_a2a, const float* __restrict__ W_a2a1,
    const float* __restrict__ W_i2h, const float* __restrict__ W_h2h,
    const float* __restrict__ W_a2h, const float* __restrict__ W_proj,
    const float* __restrict__ b1, const float* __restrict__ b2, const float* __restrict__ b3)
{
    int i = blockIdx.x * 256 + threadIdx.x;
    if (i < SEG1)      conv_one(W_a2a,  g_Wa2a_h,  g_Wa2a_l,  i - SEG0);
    else if (i < SEG2) conv_one(W_a2a1, g_Wa2a1_h, g_Wa2a1_l, i - SEG1);
    else if (i < SEG3) conv_one(W_i2h,  g_Wi_h,    g_Wi_l,    i - SEG2);
    else if (i < SEG4) conv_one(W_h2h,  g_Wh_h,    g_Wh_l,    i - SEG3);
    else if (i < SEG5) conv_one(W_a2h,  g_Wah_h,   g_Wah_l,   i - SEG4);
    else if (i < SEG6) conv_one(W_proj, g_Wp_h,    g_Wp_l,    i - SEG5);
    else if (i < SEG7) {
        int k = i - SEG6;
        float4 v1 = ((const float4*)b1)[k];
        float4 v2 = ((const float4*)b2)[k];
        float4 v3 = ((const float4*)b3)[k];
        float4 o;
        o.x = v1.x + v2.x + v3.x; o.y = v1.y + v2.y + v3.y;
        o.z = v1.z + v2.z + v3.z; o.w = v1.w + v2.w + v3.w;
        ((float4*)g_bias)[k] = o;
    }
}

// ================= SIMT sgemm for the small ah projection =================
__global__ void __launch_bounds__(256, 2) sgemm_bias(
    const float* __restrict__ Am, const float* __restrict__ Bm,
    const float* __restrict__ b1,
    float* __restrict__ C, int M, int N, int K)
{
    __shared__ __align__(16) float As[16][68];
    __shared__ __align__(16) float Bs[16][68];
    const int m0 = blockIdx.y * 64, n0 = blockIdx.x * 64;
    const int tid = threadIdx.x;
    const int tn = tid & 15, tm = tid >> 4;
    const int lrow = tid >> 2, lc = (tid & 3) << 2;

    float acc[4][4] = {};
    for (int k0 = 0; k0 < K; k0 += 16) {
        float4 av = make_float4(0.f, 0.f, 0.f, 0.f);
        float4 bv = make_float4(0.f, 0.f, 0.f, 0.f);
        if (m0 + lrow < M) av = *(const float4*)(Am + (size_t)(m0 + lrow) * K + k0 + lc);
        if (n0 + lrow < N) bv = *(const float4*)(Bm + (size_t)(n0 + lrow) * K + k0 + lc);
        __syncthreads();
        As[lc + 0][lrow] = av.x; As[lc + 1][lrow] = av.y; As[lc + 2][lrow] = av.z; As[lc + 3][lrow] = av.w;
        Bs[lc + 0][lrow] = bv.x; Bs[lc + 1][lrow] = bv.y; Bs[lc + 2][lrow] = bv.z; Bs[lc + 3][lrow] = bv.w;
        __syncthreads();
#pragma unroll
        for (int kk = 0; kk < 16; kk++) {
            float a[4], b[4];
            *(float4*)a = *(const float4*)&As[kk][tm << 2];
            *(float4*)b = *(const float4*)&Bs[kk][tn << 2];
#pragma unroll
            for (int i = 0; i < 4; i++)
#pragma unroll
                for (int j = 0; j < 4; j++)
                    acc[i][j] += a[i] * b[j];
        }
    }
#pragma unroll
    for (int j = 0; j < 4; j++) {
        int n = n0 + (tn << 2) + j;
        if (n >= N) continue;
        float bias = b1 ? b1[n] : 0.f;
#pragma unroll
        for (int i = 0; i < 4; i++) {
            int m = m0 + (tm << 2) + i;
            if (m < M) C[(size_t)m * N + n] = acc[i][j] + bias;
        }
    }
}

// ================= softmax over a + weighted sum of att rows (all 256 threads) =================
__global__ void attend_apply(const float* __restrict__ att, float* __restrict__ outres,
                             const float* __restrict__ bd, const float* __restrict__ scores)
{
    const int b = blockIdx.x, tid = threadIdx.x;  // 256 threads
    __shared__ float w[A_];
    __shared__ float rbuf[256];
    __shared__ __align__(16) float4 part[128];

    float s = -1e30f;
    if (tid < A_) {
        if (scores) {
            s = scores[b * A_ + tid];
        } else {
            const float* p = &g_spart[(size_t)(b * A_ + tid) * 4];
            s = bd[0] + p[0] + p[1] + p[2] + p[3];
        }
    }
    rbuf[tid] = s;
    __syncthreads();
    for (int off = 128; off > 0; off >>= 1) {
        if (tid < off) rbuf[tid] = fmaxf(rbuf[tid], rbuf[tid + off]);
        __syncthreads();
    }
    float mx = rbuf[0];
    __syncthreads();
    float e = (tid < A_) ? __expf(s - mx) : 0.f;
    rbuf[tid] = e;
    __syncthreads();
    for (int off = 128; off > 0; off >>= 1) {
        if (tid < off) rbuf[tid] += rbuf[tid + off];
        __syncthreads();
    }
    float inv = 1.f / rbuf[0];
    if (tid < A_) w[tid] = e * inv;
    __syncthreads();

    // weighted sum: 128 R-segments x 2 a-halves (98 each)
    const int rseg = tid & 127, half = tid >> 7;
    const float* ab = att + (size_t)b * A_ * R_ + rseg * 4;
    float4 acc = make_float4(0.f, 0.f, 0.f, 0.f);
    const int a0 = half * 98, a1 = a0 + 98;
#pragma unroll 4
    for (int a = a0; a < a1; a++) {
        float4 v = *(const float4*)(ab + (size_t)a * R_);
        float wa = w[a];
        acc.x += v.x * wa; acc.y += v.y * wa;
        acc.z += v.z * wa; acc.w += v.w * wa;
    }
    if (half) part[rseg] = acc;
    __syncthreads();
    if (!half) {
        float4 v = part[rseg];
        acc.x += v.x; acc.y += v.y; acc.z += v.z; acc.w += v.w;
        *(float4*)(outres + (size_t)b * R_ + rseg * 4) = acc;
    }
}

// ================= LSTM cell (float4, sums 3 phase slabs + bias) =================
__global__ void lstm_cell(const float* __restrict__ prev_c, float* __restrict__ out_c)
{
    int idx = blockIdx.x * 256 + threadIdx.x;     // over B*R/4
    if (idx >= B_ * R_ / 4) return;
    int b = idx >> 7;                  // R_/4 = 128
    int j4 = (idx & 127) * 4;
    const size_t base = (size_t)b * 4 * R_;

    float4 sv[4];
#pragma unroll
    for (int g = 0; g < 4; g++) {
        size_t o = base + g * R_ + j4;
        float4 v0 = *(const float4*)&g_sums[0][o];
        float4 v1 = *(const float4*)&g_sums[1][o];
        float4 v2 = *(const float4*)&g_sums[2][o];
        float4 bb = *(const float4*)&g_bias[g * R_ + j4];
        sv[g].x = v0.x + v1.x + v2.x + bb.x;
        sv[g].y = v0.y + v1.y + v2.y + bb.y;
        sv[g].z = v0.z + v1.z + v2.z + bb.z;
        sv[g].w = v0.w + v1.w + v2.w + bb.w;
    }
    float4 pc = *(const float4*)(prev_c + (size_t)b * R_ + j4);
    float4 oc, oh;
#pragma unroll
    for (int e = 0; e < 4; e++) {
        float s0 = (&sv[0].x)[e], s1 = (&sv[1].x)[e], s2 = (&sv[2].x)[e], s3 = (&sv[3].x)[e];
        float ig = 1.f / (1.f + __expf(-s0));
        float fg = 1.f / (1.f + __expf(-s1));
        float og = 1.f / (1.f + __expf(-s2));
        float gt = tanhf(s3);
        float c = fg * (&pc.x)[e] + ig * gt;
        (&oc.x)[e] = c;
        (&oh.x)[e] = og * tanhf(c);
    }
    *(float4*)(out_c + (size_t)b * R_ + j4) = oc;
    *(float4*)(g_nexth + (size_t)b * R_ + j4) = oh;
}

__global__ void add_toph(float* __restrict__ out_h)
{
    int idx = blockIdx.x * 256 + threadIdx.x;
    if (idx >= B_ * R_) return;
    out_h[idx] = g_attres[idx] + g_nexth[idx];
}

// ================= log_softmax: online (max,sum) pass + write pass =================
__global__ void log_softmax_kernel(float* __restrict__ logits, const float* __restrict__ bias)
{
    const int b = blockIdx.x, tid = threadIdx.x;  // 512 threads
    float* row = logits + (size_t)b * V_;
    __shared__ float rm[512], rd[512];

    float m = -1e30f, d = 0.f;
    for (int i = tid; i < V_; i += 512) {
        float v = row[i] + bias[i];
        if (v > m) { d = d * __expf(m - v) + 1.f; m = v; }
        else d += __expf(v - m);
    }
    rm[tid] = m; rd[tid] = d;
    __syncthreads();
    for (int off = 256; off > 0; off >>= 1) {
        if (tid < off) {
            float m2 = rm[tid + off], d2 = rd[tid + off];
            float mo = fmaxf(rm[tid], m2);
            rd[tid] = rd[tid] * __expf(rm[tid] - mo) + d2 * __expf(m2 - mo);
            rm[tid] = mo;
        }
        __syncthreads();
    }
    float lse = rm[0] + logf(rd[0]);
    for (int i = tid; i < V_; i += 512) row[i] = row[i] + bias[i] - lse;
}

// ================= host launch =================
extern "C" void kernel_launch(void* const* d_in, const int* in_sizes, int n_in,
                              void* d_out, int out_size)
{
    const float* x      = (const float*)d_in[0];
    const float* att    = (const float*)d_in[1];
    const float* prev_c = (const float*)d_in[2];
    const float* prev_h = (const float*)d_in[3];
    const float* W_a2a  = (const float*)d_in[4];  const float* b_a2a  = (const float*)d_in[5];
    const float* W_h2a  = (const float*)d_in[6];  const float* b_h2a  = (const float*)d_in[7];
    const float* W_d2d  = (const float*)d_in[8];  const float* b_d2d  = (const float*)d_in[9];
    const float* W_i2h  = (const float*)d_in[10]; const float* b_i2h  = (const float*)d_in[11];
    const float* W_a2h  = (const float*)d_in[12]; const float* b_a2h  = (const float*)d_in[13];
    const float* W_h2h  = (const float*)d_in[14]; const float* b_h2h  = (const float*)d_in[15];
    const float* W_a2a1 = (const float*)d_in[16]; const float* b_a2a1 = (const float*)d_in[17];
    const float* W_h2a1 = (const float*)d_in[18]; const float* b_h2a1 = (const float*)d_in[19];
    const float* W_d2d1 = (const float*)d_in[20]; const float* b_d2d1 = (const float*)d_in[21];
    const float* W_proj = (const float*)d_in[22]; const float* b_proj = (const float*)d_in[23];

    float* out   = (float*)d_out;
    float* out_c = out;                  // next_c  [B,R]
    float* out_h = out + B_ * R_;        // top_h   [B,R]
    float* out_l = out + 2 * B_ * R_;    // logsoft [B,V]

    float *ah_p, *attres_p, *nexth_p, *sums_p, *score1_p;
    cudaGetSymbolAddress((void**)&ah_p,     g_ah);
    cudaGetSymbolAddress((void**)&attres_p, g_attres);
    cudaGetSymbolAddress((void**)&nexth_p,  g_nexth);
    cudaGetSymbolAddress((void**)&sums_p,   g_sums);
    cudaGetSymbolAddress((void**)&score1_p, g_score1);

    __nv_bfloat16 *Wa2a_h, *Wa2a_l, *Wa2a1_h, *Wa2a1_l, *Wi_h, *Wi_l, *Wh_h, *Wh_l, *Wah_h, *Wah_l, *Wp_h, *Wp_l;
    cudaGetSymbolAddress((void**)&Wa2a_h,  g_Wa2a_h);  cudaGetSymbolAddress((void**)&Wa2a_l,  g_Wa2a_l);
    cudaGetSymbolAddress((void**)&Wa2a1_h, g_Wa2a1_h); cudaGetSymbolAddress((void**)&Wa2a1_l, g_Wa2a1_l);
    cudaGetSymbolAddress((void**)&Wi_h,    g_Wi_h);    cudaGetSymbolAddress((void**)&Wi_l,    g_Wi_l);
    cudaGetSymbolAddress((void**)&Wh_h,    g_Wh_h);    cudaGetSymbolAddress((void**)&Wh_l,    g_Wh_l);
    cudaGetSymbolAddress((void**)&Wah_h,   g_Wah_h);   cudaGetSymbolAddress((void**)&Wah_l,   g_Wah_l);
    cudaGetSymbolAddress((void**)&Wp_h,    g_Wp_h);    cudaGetSymbolAddress((void**)&Wp_l,    g_Wp_l);

    cudaFuncSetAttribute(attend_dual, cudaFuncAttributeMaxDynamicSharedMemorySize, SMEM_DUAL);
    cudaFuncSetAttribute(tc_gemm,     cudaFuncAttributeMaxDynamicSharedMemorySize, SMEM_GEMM);

    const dim3 blk(256);

    // ---- all weight conversions + gate bias in one launch ----
    conv_all<<<CONV_BLOCKS, blk>>>(W_a2a, W_a2a1, W_i2h, W_h2h, W_a2h, W_proj,
                                   b_i2h, b_h2h, b_a2h);

    // ---- ah0 + fused dual attend GEMM ----
    sgemm_bias<<<dim3((A_ + 63) / 64, (B_ + 63) / 64), blk>>>(prev_h, W_h2a, b_h2a, ah_p, B_, A_, R_);
    attend_dual<<<dim3(4, (B_ * A_) / 128), blk, SMEM_DUAL>>>(
        att, Wa2a_h, Wa2a_l, Wa2a1_h, Wa2a1_l, b_a2a, W_d2d);
    attend_apply<<<B_, blk>>>(att, attres_p, b_d2d, nullptr);

    // ---- LSTM gates (3 phases in grid.z) + cell ----
    tc_gemm<<<dim3(16, 2, 3), blk, SMEM_GEMM>>>(
        x, prev_h, attres_p,
        Wi_h, Wi_l, Wh_h, Wh_l, Wah_h, Wah_l,
        4 * R_, sums_p, 4 * R_, (size_t)B_ * 4 * R_);
    lstm_cell<<<(B_ * R_ / 4 + 255) / 256, blk>>>(prev_c, out_c);

    // ---- attend #1 finish (cheap) ----
    sgemm_bias<<<dim3((A_ + 63) / 64, (B_ + 63) / 64), blk>>>(nexth_p, W_h2a1, b_h2a1, ah_p, B_, A_, R_);
    attend1_score<<<(B_ * A_ * 32 + 255) / 256, blk>>>(b_a2a1, W_d2d1, b_d2d1);
    attend_apply<<<B_, blk>>>(att, attres_p, nullptr, score1_p);

    // ---- top_h, projection, log_softmax ----
    add_toph<<<(B_ * R_ + 255) / 256, blk>>>(out_h);
    tc_gemm<<<dim3((V_ + 127) / 128, 2, 1), blk, SMEM_GEMM>>>(
        out_h, nullptr, nullptr,
        Wp_h, Wp_l, nullptr, nullptr, nullptr, nullptr,
        V_, out_l, V_, 0);
    log_softmax_kernel<<<B_, 512>>>(out_l, b_proj);
}

// round 15
// speedup vs baseline: 1.4735x; 1.0118x over previous
#include <cuda_runtime.h>
#include <cuda_bf16.h>
#include <mma.h>
#include <cstdint>

using namespace nvcuda;

#define B_ 256
#define I_ 512
#define R_ 512
#define A_ 196
#define V_ 10000

// ================= scratch (static device; no allocation allowed) =================
__device__ float g_ah[B_ * A_];            // [B, A]
__device__ float g_spart[B_ * A_ * 4];     // attend0 score partials (2 nblocks x 2 halves)
__device__ float g_score1[B_ * A_];        // attend1 scores
__device__ float g_av1[B_ * A_ * 256];     // raw att.Wa2a1^T (padded N=256), 51.4MB
__device__ float g_attres[B_ * R_];        // [B, R]
__device__ float g_sums[3][B_ * 4 * R_];   // per-phase gate GEMM results
__device__ float g_nexth[B_ * R_];         // [B, R]
__device__ float g_bias[4 * R_];           // combined gate bias

// split-bf16 weight caches
__device__ __nv_bfloat16 g_Wa2a_h[A_ * R_],  g_Wa2a_l[A_ * R_];
__device__ __nv_bfloat16 g_Wa2a1_h[A_ * R_], g_Wa2a1_l[A_ * R_];
__device__ __nv_bfloat16 g_Wi_h[4 * R_ * I_], g_Wi_l[4 * R_ * I_];
__device__ __nv_bfloat16 g_Wh_h[4 * R_ * R_], g_Wh_l[4 * R_ * R_];
__device__ __nv_bfloat16 g_Wah_h[4 * R_ * R_], g_Wah_l[4 * R_ * R_];
__device__ __nv_bfloat16 g_Wp_h[V_ * R_], g_Wp_l[V_ * R_];

// smem staging (bf16 elems, ld = 40); tile = 128x32 = 5120 elems
// A single-buffered, B double-buffered (cp.async)
#define LDT 40
#define OFF_AH  0
#define OFF_AL  5120
#define OFF_B0H 10240
#define OFF_B0L 15360
#define OFF_B1H 20480
#define OFF_B1L 25600
#define SMEM_GEMM 61440
#define SMEM_DUAL 69632   // max(staging 61440, 128x132 fp32 C tile 67584)

// pack 16 floats -> 2x uint4 hi + 2x uint4 lo (8 bf16 per uint4)
__device__ __forceinline__ void split16(const float* f, uint4* H, uint4* L) {
    __align__(16) unsigned short hs[16];
    __align__(16) unsigned short ls[16];
#pragma unroll
    for (int e = 0; e < 16; e++) {
        __nv_bfloat16 h = __float2bfloat16_rn(f[e]);
        hs[e] = __bfloat16_as_ushort(h);
        ls[e] = __bfloat16_as_ushort(__float2bfloat16_rn(f[e] - __bfloat162float(h)));
    }
    H[0] = ((uint4*)hs)[0]; H[1] = ((uint4*)hs)[1];
    L[0] = ((uint4*)ls)[0]; L[1] = ((uint4*)ls)[1];
}

__device__ __forceinline__ uint32_t smem_u32(const void* p) {
    uint32_t a;
    asm("{ .reg .u64 t; cvta.to.shared.u64 t, %1; cvt.u32.u64 %0, t; }" : "=r"(a) : "l"(p));
    return a;
}
// cp.async 16B with zero-fill when src_sz == 0
__device__ __forceinline__ void cp16(uint32_t dst, const void* src, int src_sz) {
    asm volatile("cp.async.cg.shared.global [%0], [%1], 16, %2;"
                 :: "r"(dst), "l"(src), "r"(src_sz));
}
__device__ __forceinline__ void cp_commit() { asm volatile("cp.async.commit_group;"); }
__device__ __forceinline__ void cp_wait1() { asm volatile("cp.async.wait_group 1;"); }
__device__ __forceinline__ void cp_wait0() { asm volatile("cp.async.wait_group 0;"); }

// ---- shared MMA inner step over staged tiles ----
__device__ __forceinline__ void mma_tiles(
    const __nv_bfloat16* sAH, const __nv_bfloat16* sAL,
    const __nv_bfloat16* sBH, const __nv_bfloat16* sBL,
    int wm, int wn, wmma::fragment<wmma::accumulator, 16, 16, 16, float> acc[4][2])
{
#pragma unroll
    for (int ks = 0; ks < 2; ks++) {
        wmma::fragment<wmma::matrix_a, 16, 16, 16, __nv_bfloat16, wmma::row_major> fah[4], fal[4];
#pragma unroll
        for (int i = 0; i < 4; i++) {
            wmma::load_matrix_sync(fah[i], sAH + (wm * 64 + i * 16) * LDT + ks * 16, LDT);
            wmma::load_matrix_sync(fal[i], sAL + (wm * 64 + i * 16) * LDT + ks * 16, LDT);
        }
#pragma unroll
        for (int j = 0; j < 2; j++) {
            wmma::fragment<wmma::matrix_b, 16, 16, 16, __nv_bfloat16, wmma::col_major> fbh, fbl;
            wmma::load_matrix_sync(fbh, sBH + (wn * 32 + j * 16) * LDT + ks * 16, LDT);
            wmma::load_matrix_sync(fbl, sBL + (wn * 32 + j * 16) * LDT + ks * 16, LDT);
#pragma unroll
            for (int i = 0; i < 4; i++) {
                wmma::mma_sync(acc[i][j], fah[i], fbh, acc[i][j]);
                wmma::mma_sync(acc[i][j], fah[i], fbl, acc[i][j]);
                wmma::mma_sync(acc[i][j], fal[i], fbh, acc[i][j]);
            }
        }
    }
}

// ================= fused dual-attend GEMM (round-9 winner, unchanged) =================
// grid (4, BA/128). bx 0,1: C0 = att.Wa2a^T -> tanh/Wd epilogue -> g_spart.
// bx 2,3: C1 = att.Wa2a1^T -> raw store to g_av1 (ld 256).
__global__ void __launch_bounds__(256) attend_dual(
    const float* __restrict__ att,
    const __nv_bfloat16* __restrict__ W0h, const __nv_bfloat16* __restrict__ W0l,
    const __nv_bfloat16* __restrict__ W1h, const __nv_bfloat16* __restrict__ W1l,
    const float* __restrict__ ba0, const float* __restrict__ Wd0)
{
    extern __shared__ char smem[];
    __nv_bfloat16* sAH = (__nv_bfloat16*)smem + OFF_AH;
    __nv_bfloat16* sAL = (__nv_bfloat16*)smem + OFF_AL;

    const int tid = threadIdx.x;
    const int wid = tid >> 5;
    const int wm = wid >> 2, wn = wid & 3;
    const int bx = blockIdx.x;
    const int m0 = blockIdx.y * 128;
    const bool second = (bx >= 2);
    const int n0 = (bx & 1) * 128;
    const __nv_bfloat16* Bh = second ? W1h : W0h;
    const __nv_bfloat16* Bl = second ? W1l : W0l;

    wmma::fragment<wmma::accumulator, 16, 16, 16, float> acc[4][2];
#pragma unroll
    for (int i = 0; i < 4; i++)
#pragma unroll
        for (int j = 0; j < 2; j++) wmma::fill_fragment(acc[i][j], 0.0f);

    const int r  = tid >> 1;
    const int ch = (tid & 1) * 16;
    const int Brow = n0 + r;
    const bool bvalid = (Brow < A_);
    const int BrowC = bvalid ? Brow : 0;
    const int psz = bvalid ? 16 : 0;

    const uint32_t sbase = smem_u32(smem);
    const uint32_t rowoff = (uint32_t)(r * LDT + ch) * 2;
    const uint32_t dBH[2] = { sbase + OFF_B0H * 2 + rowoff, sbase + OFF_B1H * 2 + rowoff };
    const uint32_t dBL[2] = { sbase + OFF_B0L * 2 + rowoff, sbase + OFF_B1L * 2 + rowoff };

    // prologue: B chunk 0 -> buf 0
    {
        const __nv_bfloat16* ph = Bh + (size_t)BrowC * 512 + ch;
        const __nv_bfloat16* pl = Bl + (size_t)BrowC * 512 + ch;
        cp16(dBH[0], ph, psz); cp16(dBH[0] + 16, ph + 8, psz);
        cp16(dBL[0], pl, psz); cp16(dBL[0] + 16, pl + 8, psz);
        cp_commit();
    }

    for (int kc = 0; kc < 16; kc++) {
        __syncthreads();   // prev MMA done: A buf + B[next] buf free
        // ---- A: fp32 -> split bf16 ----
        {
            __align__(16) float f[16];
            const float4* src = (const float4*)(att + (size_t)(m0 + r) * 512 + kc * 32 + ch);
            ((float4*)f)[0] = src[0]; ((float4*)f)[1] = src[1];
            ((float4*)f)[2] = src[2]; ((float4*)f)[3] = src[3];
            uint4 H[2], L[2];
            split16(f, H, L);
            *(uint4*)(sAH + r * LDT + ch)     = H[0];
            *(uint4*)(sAH + r * LDT + ch + 8) = H[1];
            *(uint4*)(sAL + r * LDT + ch)     = L[0];
            *(uint4*)(sAL + r * LDT + ch + 8) = L[1];
        }
        // ---- B: cp.async next chunk into other buffer ----
        if (kc < 15) {
            const int k0 = (kc + 1) * 32;
            const int buf = (kc + 1) & 1;
            const __nv_bfloat16* ph = Bh + (size_t)BrowC * 512 + k0 + ch;
            const __nv_bfloat16* pl = Bl + (size_t)BrowC * 512 + k0 + ch;
            cp16(dBH[buf], ph, psz); cp16(dBH[buf] + 16, ph + 8, psz);
            cp16(dBL[buf], pl, psz); cp16(dBL[buf] + 16, pl + 8, psz);
            cp_commit();
            cp_wait1();
        } else {
            cp_wait0();
        }
        __syncthreads();
        const __nv_bfloat16* sBH = (__nv_bfloat16*)smem + ((kc & 1) ? OFF_B1H : OFF_B0H);
        const __nv_bfloat16* sBL = (__nv_bfloat16*)smem + ((kc & 1) ? OFF_B1L : OFF_B0L);
        mma_tiles(sAH, sAL, sBH, sBL, wm, wn, acc);
    }

    if (second) {
        float* outz = g_av1 + (size_t)m0 * 256;
#pragma unroll
        for (int i = 0; i < 4; i++)
#pragma unroll
            for (int j = 0; j < 2; j++)
                wmma::store_matrix_sync(outz + (size_t)(wm * 64 + i * 16) * 256 + n0 + wn * 32 + j * 16,
                                        acc[i][j], 256, wmma::mem_row_major);
    } else {
        __syncthreads();
        float* Cs = (float*)smem;   // [128][132]
#pragma unroll
        for (int i = 0; i < 4; i++)
#pragma unroll
            for (int j = 0; j < 2; j++)
                wmma::store_matrix_sync(Cs + (wm * 64 + i * 16) * 132 + wn * 32 + j * 16,
                                        acc[i][j], 132, wmma::mem_row_major);
        __syncthreads();
        const int half = tid & 1;
        const int c0 = half * 64;
        float ahm = g_ah[m0 + r];
        float p = 0.f;
#pragma unroll 4
        for (int c = 0; c < 64; c++) {
            int o = n0 + c0 + c;
            if (o < A_)
                p += tanhf(Cs[r * 132 + c0 + c] + ba0[o] + ahm) * Wd0[o];
        }
        g_spart[(size_t)(m0 + r) * 4 + bx * 2 + half] = p;
    }
}

// ================= attend1 finish: scores from stored av1 =================
__global__ void attend1_score(const float* __restrict__ ba, const float* __restrict__ Wd,
                              const float* __restrict__ bd)
{
    const int w = (blockIdx.x * blockDim.x + threadIdx.x) >> 5;   // global warp = row
    const int lane = threadIdx.x & 31;
    if (w >= B_ * A_) return;
    const float* row = g_av1 + (size_t)w * 256;
    float ahm = g_ah[w];
    float p = 0.f;
#pragma unroll
    for (int it = 0; it < 7; it++) {
        int o = it * 32 + lane;
        if (o < A_) p += tanhf(row[o] + ba[o] + ahm) * Wd[o];
    }
#pragma unroll
    for (int off = 16; off > 0; off >>= 1)
        p += __shfl_down_sync(0xffffffff, p, off);
    if (lane == 0) g_score1[w] = p + bd[0];
}

// ================= gates / proj GEMM (round-9 winner, unchanged) =================
__global__ void __launch_bounds__(256, 2) tc_gemm(
    const float* __restrict__ A0, const float* __restrict__ A1, const float* __restrict__ A2,
    const __nv_bfloat16* __restrict__ Bh0, const __nv_bfloat16* __restrict__ Bl0,
    const __nv_bfloat16* __restrict__ Bh1, const __nv_bfloat16* __restrict__ Bl1,
    const __nv_bfloat16* __restrict__ Bh2, const __nv_bfloat16* __restrict__ Bl2,
    int Ntot, float* __restrict__ out, int ldout, size_t zstride)
{
    extern __shared__ char smem[];
    __nv_bfloat16* sAH = (__nv_bfloat16*)smem + OFF_AH;
    __nv_bfloat16* sAL = (__nv_bfloat16*)smem + OFF_AL;

    const int tid = threadIdx.x;
    const int wid = tid >> 5;
    const int wm = wid >> 2, wn = wid & 3;
    const int m0 = blockIdx.y * 128, n0 = blockIdx.x * 128;
    const int z = blockIdx.z;

    const float* Ap = (z == 0) ? A0 : (z == 1) ? A1 : A2;
    const __nv_bfloat16* Bh = (z == 0) ? Bh0 : (z == 1) ? Bh1 : Bh2;
    const __nv_bfloat16* Bl = (z == 0) ? Bl0 : (z == 1) ? Bl1 : Bl2;

    wmma::fragment<wmma::accumulator, 16, 16, 16, float> acc[4][2];
#pragma unroll
    for (int i = 0; i < 4; i++)
#pragma unroll
        for (int j = 0; j < 2; j++) wmma::fill_fragment(acc[i][j], 0.0f);

    const int r  = tid >> 1;
    const int ch = (tid & 1) * 16;
    const int Brow = n0 + r;
    const bool bvalid = (Brow < Ntot);
    const int BrowC = bvalid ? Brow : 0;
    const int psz = bvalid ? 16 : 0;

    const uint32_t sbase = smem_u32(smem);
    const uint32_t rowoff = (uint32_t)(r * LDT + ch) * 2;
    const uint32_t dBH[2] = { sbase + OFF_B0H * 2 + rowoff, sbase + OFF_B1H * 2 + rowoff };
    const uint32_t dBL[2] = { sbase + OFF_B0L * 2 + rowoff, sbase + OFF_B1L * 2 + rowoff };

    {
        const __nv_bfloat16* ph = Bh + (size_t)BrowC * 512 + ch;
        const __nv_bfloat16* pl = Bl + (size_t)BrowC * 512 + ch;
        cp16(dBH[0], ph, psz); cp16(dBH[0] + 16, ph + 8, psz);
        cp16(dBL[0], pl, psz); cp16(dBL[0] + 16, pl + 8, psz);
        cp_commit();
    }

    for (int kc = 0; kc < 16; kc++) {
        __syncthreads();
        {
            __align__(16) float f[16];
            const float4* src = (const float4*)(Ap + (size_t)(m0 + r) * 512 + kc * 32 + ch);
            ((float4*)f)[0] = src[0]; ((float4*)f)[1] = src[1];
            ((float4*)f)[2] = src[2]; ((float4*)f)[3] = src[3];
            uint4 H[2], L[2];
            split16(f, H, L);
            *(uint4*)(sAH + r * LDT + ch)     = H[0];
            *(uint4*)(sAH + r * LDT + ch + 8) = H[1];
            *(uint4*)(sAL + r * LDT + ch)     = L[0];
            *(uint4*)(sAL + r * LDT + ch + 8) = L[1];
        }
        if (kc < 15) {
            const int k0 = (kc + 1) * 32;
            const int buf = (kc + 1) & 1;
            const __nv_bfloat16* ph = Bh + (size_t)BrowC * 512 + k0 + ch;
            const __nv_bfloat16* pl = Bl + (size_t)BrowC * 512 + k0 + ch;
            cp16(dBH[buf], ph, psz); cp16(dBH[buf] + 16, ph + 8, psz);
            cp16(dBL[buf], pl, psz); cp16(dBL[buf] + 16, pl + 8, psz);
            cp_commit();
            cp_wait1();
        } else {
            cp_wait0();
        }
        __syncthreads();
        const __nv_bfloat16* sBH = (__nv_bfloat16*)smem + ((kc & 1) ? OFF_B1H : OFF_B0H);
        const __nv_bfloat16* sBL = (__nv_bfloat16*)smem + ((kc & 1) ? OFF_B1L : OFF_B0L);
        mma_tiles(sAH, sAL, sBH, sBL, wm, wn, acc);
    }

    float* outz = out + (size_t)z * zstride;
#pragma unroll
    for (int i = 0; i < 4; i++) {
        int mrow = m0 + wm * 64 + i * 16;
#pragma unroll
        for (int j = 0; j < 2; j++) {
            int ncol = n0 + wn * 32 + j * 16;
            if (ncol + 16 <= Ntot)
                wmma::store_matrix_sync(outz + (size_t)mrow * ldout + ncol, acc[i][j],
                                        ldout, wmma::mem_row_major);
        }
    }
}

// ================= fused conversion: all weights + gate bias in ONE launch =================
#define C_A2A   (A_ * R_ / 4)
#define C_BIG   (4 * R_ * R_ / 4)
#define C_PROJ  (V_ * R_ / 4)
#define SEG0 0
#define SEG1 (SEG0 + C_A2A)
#define SEG2 (SEG1 + C_A2A)
#define SEG3 (SEG2 + C_BIG)
#define SEG4 (SEG3 + C_BIG)
#define SEG5 (SEG4 + C_BIG)
#define SEG6 (SEG5 + C_PROJ)
#define SEG7 (SEG6 + (4 * R_ / 4))
#define CONV_BLOCKS (SEG7 / 256)

__device__ __forceinline__ void conv_one(const float* __restrict__ src,
                                         __nv_bfloat16* __restrict__ hi,
                                         __nv_bfloat16* __restrict__ lo, int i)
{
    float4 v = ((const float4*)src)[i];
    __nv_bfloat16 hx = __float2bfloat16_rn(v.x), hy = __float2bfloat16_rn(v.y);
    __nv_bfloat16 hz = __float2bfloat16_rn(v.z), hw = __float2bfloat16_rn(v.w);
    __nv_bfloat16 lx = __float2bfloat16_rn(v.x - __bfloat162float(hx));
    __nv_bfloat16 ly = __float2bfloat16_rn(v.y - __bfloat162float(hy));
    __nv_bfloat16 lz = __float2bfloat16_rn(v.z - __bfloat162float(hz));
    __nv_bfloat16 lw = __float2bfloat16_rn(v.w - __bfloat16_as_ushort(hw) * 0);
    lw = __float2bfloat16_rn(v.w - __bfloat162float(hw));
    uint2 H, L;
    H.x = (uint32_t)__bfloat16_as_ushort(hx) | ((uint32_t)__bfloat16_as_ushort(hy) << 16);
    H.y = (uint32_t)__bfloat16_as_ushort(hz) | ((uint32_t)__bfloat16_as_ushort(hw) << 16);
    L.x = (uint32_t)__bfloat16_as_ushort(lx) | ((uint32_t)__bfloat16_as_ushort(ly) << 16);
    L.y = (uint32_t)__bfloat16_as_ushort(lz) | ((uint32_t)__bfloat16_as_ushort(lw) << 16);
    ((uint2*)hi)[i] = H;
    ((uint2*)lo)[i] = L;
}

__global__ void conv_all(
    const float* __restrict__ W_a2a, const float* __restrict__ W_a2a1,
    const float* __restrict__ W_i2h, const float* __restrict__ W_h2h,
    const float* __restrict__ W_a2h, const float* __restrict__ W_proj,
    const float* __restrict__ b1, const float* __restrict__ b2, const float* __restrict__ b3)
{
    int i = blockIdx.x * 256 + threadIdx.x;
    if (i < SEG1)      conv_one(W_a2a,  g_Wa2a_h,  g_Wa2a_l,  i - SEG0);
    else if (i < SEG2) conv_one(W_a2a1, g_Wa2a1_h, g_Wa2a1_l, i - SEG1);
    else if (i < SEG3) conv_one(W_i2h,  g_Wi_h,    g_Wi_l,    i - SEG2);
    else if (i < SEG4) conv_one(W_h2h,  g_Wh_h,    g_Wh_l,    i - SEG3);
    else if (i < SEG5) conv_one(W_a2h,  g_Wah_h,   g_Wah_l,   i - SEG4);
    else if (i < SEG6) conv_one(W_proj, g_Wp_h,    g_Wp_l,    i - SEG5);
    else if (i < SEG7) {
        int k = i - SEG6;
        float4 v1 = ((const float4*)b1)[k];
        float4 v2 = ((const float4*)b2)[k];
        float4 v3 = ((const float4*)b3)[k];
        float4 o;
        o.x = v1.x + v2.x + v3.x; o.y = v1.y + v2.y + v3.y;
        o.z = v1.z + v2.z + v3.z; o.w = v1.w + v2.w + v3.w;
        ((float4*)g_bias)[k] = o;
    }
}

// ================= SIMT sgemm for the small ah projection =================
__global__ void __launch_bounds__(256, 2) sgemm_bias(
    const float* __restrict__ Am, const float* __restrict__ Bm,
    const float* __restrict__ b1,
    float* __restrict__ C, int M, int N, int K)
{
    __shared__ __align__(16) float As[16][68];
    __shared__ __align__(16) float Bs[16][68];
    const int m0 = blockIdx.y * 64, n0 = blockIdx.x * 64;
    const int tid = threadIdx.x;
    const int tn = tid & 15, tm = tid >> 4;
    const int lrow = tid >> 2, lc = (tid & 3) << 2;

    float acc[4][4] = {};
    for (int k0 = 0; k0 < K; k0 += 16) {
        float4 av = make_float4(0.f, 0.f, 0.f, 0.f);
        float4 bv = make_float4(0.f, 0.f, 0.f, 0.f);
        if (m0 + lrow < M) av = *(const float4*)(Am + (size_t)(m0 + lrow) * K + k0 + lc);
        if (n0 + lrow < N) bv = *(const float4*)(Bm + (size_t)(n0 + lrow) * K + k0 + lc);
        __syncthreads();
        As[lc + 0][lrow] = av.x; As[lc + 1][lrow] = av.y; As[lc + 2][lrow] = av.z; As[lc + 3][lrow] = av.w;
        Bs[lc + 0][lrow] = bv.x; Bs[lc + 1][lrow] = bv.y; Bs[lc + 2][lrow] = bv.z; Bs[lc + 3][lrow] = bv.w;
        __syncthreads();
#pragma unroll
        for (int kk = 0; kk < 16; kk++) {
            float a[4], b[4];
            *(float4*)a = *(const float4*)&As[kk][tm << 2];
            *(float4*)b = *(const float4*)&Bs[kk][tn << 2];
#pragma unroll
            for (int i = 0; i < 4; i++)
#pragma unroll
                for (int j = 0; j < 4; j++)
                    acc[i][j] += a[i] * b[j];
        }
    }
#pragma unroll
    for (int j = 0; j < 4; j++) {
        int n = n0 + (tn << 2) + j;
        if (n >= N) continue;
        float bias = b1 ? b1[n] : 0.f;
#pragma unroll
        for (int i = 0; i < 4; i++) {
            int m = m0 + (tm << 2) + i;
            if (m < M) C[(size_t)m * N + n] = acc[i][j] + bias;
        }
    }
}

// ================= softmax over a + weighted sum of att rows (512 threads) =================
// threads: 128 R-segments x 4 a-quarters (49 each)
__global__ void __launch_bounds__(512) attend_apply(
    const float* __restrict__ att, float* __restrict__ outres,
    const float* __restrict__ bd, const float* __restrict__ scores)
{
    const int b = blockIdx.x, tid = threadIdx.x;  // 512 threads
    __shared__ float w[A_];
    __shared__ float rbuf[512];
    __shared__ __align__(16) float4 part[3][128];

    float s = -1e30f;
    if (tid < A_) {
        if (scores) {
            s = scores[b * A_ + tid];
        } else {
            const float* p = &g_spart[(size_t)(b * A_ + tid) * 4];
            s = bd[0] + p[0] + p[1] + p[2] + p[3];
        }
    }
    rbuf[tid] = s;
    __syncthreads();
    for (int off = 256; off > 0; off >>= 1) {
        if (tid < off) rbuf[tid] = fmaxf(rbuf[tid], rbuf[tid + off]);
        __syncthreads();
    }
    float mx = rbuf[0];
    __syncthreads();
    float e = (tid < A_) ? __expf(s - mx) : 0.f;
    rbuf[tid] = e;
    __syncthreads();
    for (int off = 256; off > 0; off >>= 1) {
        if (tid < off) rbuf[tid] += rbuf[tid + off];
        __syncthreads();
    }
    float inv = 1.f / rbuf[0];
    if (tid < A_) w[tid] = e * inv;
    __syncthreads();

    // weighted sum: 128 R-segments x 4 a-quarters (49 each)
    const int rseg = tid & 127, aq = tid >> 7;
    const float* ab = att + (size_t)b * A_ * R_ + rseg * 4;
    float4 acc = make_float4(0.f, 0.f, 0.f, 0.f);
    const int a0 = aq * 49, a1 = a0 + 49;
#pragma unroll 7
    for (int a = a0; a < a1; a++) {
        float4 v = *(const float4*)(ab + (size_t)a * R_);
        float wa = w[a];
        acc.x += v.x * wa; acc.y += v.y * wa;
        acc.z += v.z * wa; acc.w += v.w * wa;
    }
    if (aq > 0) part[aq - 1][rseg] = acc;
    __syncthreads();
    if (aq == 0) {
#pragma unroll
        for (int p = 0; p < 3; p++) {
            float4 v = part[p][rseg];
            acc.x += v.x; acc.y += v.y; acc.z += v.z; acc.w += v.w;
        }
        *(float4*)(outres + (size_t)b * R_ + rseg * 4) = acc;
    }
}

// ================= LSTM cell (float4, sums 3 phase slabs + bias) =================
__global__ void lstm_cell(const float* __restrict__ prev_c, float* __restrict__ out_c)
{
    int idx = blockIdx.x * 256 + threadIdx.x;     // over B*R/4
    if (idx >= B_ * R_ / 4) return;
    int b = idx >> 7;                  // R_/4 = 128
    int j4 = (idx & 127) * 4;
    const size_t base = (size_t)b * 4 * R_;

    float4 sv[4];
#pragma unroll
    for (int g = 0; g < 4; g++) {
        size_t o = base + g * R_ + j4;
        float4 v0 = *(const float4*)&g_sums[0][o];
        float4 v1 = *(const float4*)&g_sums[1][o];
        float4 v2 = *(const float4*)&g_sums[2][o];
        float4 bb = *(const float4*)&g_bias[g * R_ + j4];
        sv[g].x = v0.x + v1.x + v2.x + bb.x;
        sv[g].y = v0.y + v1.y + v2.y + bb.y;
        sv[g].z = v0.z + v1.z + v2.z + bb.z;
        sv[g].w = v0.w + v1.w + v2.w + bb.w;
    }
    float4 pc = *(const float4*)(prev_c + (size_t)b * R_ + j4);
    float4 oc, oh;
#pragma unroll
    for (int e = 0; e < 4; e++) {
        float s0 = (&sv[0].x)[e], s1 = (&sv[1].x)[e], s2 = (&sv[2].x)[e], s3 = (&sv[3].x)[e];
        float ig = 1.f / (1.f + __expf(-s0));
        float fg = 1.f / (1.f + __expf(-s1));
        float og = 1.f / (1.f + __expf(-s2));
        float gt = tanhf(s3);
        float c = fg * (&pc.x)[e] + ig * gt;
        (&oc.x)[e] = c;
        (&oh.x)[e] = og * tanhf(c);
    }
    *(float4*)(out_c + (size_t)b * R_ + j4) = oc;
    *(float4*)(g_nexth + (size_t)b * R_ + j4) = oh;
}

__global__ void add_toph(float* __restrict__ out_h)
{
    int idx = blockIdx.x * 256 + threadIdx.x;
    if (idx >= B_ * R_) return;
    out_h[idx] = g_attres[idx] + g_nexth[idx];
}

// ================= log_softmax: online (max,sum) pass + write pass =================
__global__ void log_softmax_kernel(float* __restrict__ logits, const float* __restrict__ bias)
{
    const int b = blockIdx.x, tid = threadIdx.x;  // 512 threads
    float* row = logits + (size_t)b * V_;
    __shared__ float rm[512], rd[512];

    float m = -1e30f, d = 0.f;
    for (int i = tid; i < V_; i += 512) {
        float v = row[i] + bias[i];
        if (v > m) { d = d * __expf(m - v) + 1.f; m = v; }
        else d += __expf(v - m);
    }
    rm[tid] = m; rd[tid] = d;
    __syncthreads();
    for (int off = 256; off > 0; off >>= 1) {
        if (tid < off) {
            float m2 = rm[tid + off], d2 = rd[tid + off];
            float mo = fmaxf(rm[tid], m2);
            rd[tid] = rd[tid] * __expf(rm[tid] - mo) + d2 * __expf(m2 - mo);
            rm[tid] = mo;
        }
        __syncthreads();
    }
    float lse = rm[0] + logf(rd[0]);
    for (int i = tid; i < V_; i += 512) row[i] = row[i] + bias[i] - lse;
}

// ================= host launch =================
extern "C" void kernel_launch(void* const* d_in, const int* in_sizes, int n_in,
                              void* d_out, int out_size)
{
    const float* x      = (const float*)d_in[0];
    const float* att    = (const float*)d_in[1];
    const float* prev_c = (const float*)d_in[2];
    const float* prev_h = (const float*)d_in[3];
    const float* W_a2a  = (const float*)d_in[4];  const float* b_a2a  = (const float*)d_in[5];
    const float* W_h2a  = (const float*)d_in[6];  const float* b_h2a  = (const float*)d_in[7];
    const float* W_d2d  = (const float*)d_in[8];  const float* b_d2d  = (const float*)d_in[9];
    const float* W_i2h  = (const float*)d_in[10]; const float* b_i2h  = (const float*)d_in[11];
    const float* W_a2h  = (const float*)d_in[12]; const float* b_a2h  = (const float*)d_in[13];
    const float* W_h2h  = (const float*)d_in[14]; const float* b_h2h  = (const float*)d_in[15];
    const float* W_a2a1 = (const float*)d_in[16]; const float* b_a2a1 = (const float*)d_in[17];
    const float* W_h2a1 = (const float*)d_in[18]; const float* b_h2a1 = (const float*)d_in[19];
    const float* W_d2d1 = (const float*)d_in[20]; const float* b_d2d1 = (const float*)d_in[21];
    const float* W_proj = (const float*)d_in[22]; const float* b_proj = (const float*)d_in[23];

    float* out   = (float*)d_out;
    float* out_c = out;                  // next_c  [B,R]
    float* out_h = out + B_ * R_;        // top_h   [B,R]
    float* out_l = out + 2 * B_ * R_;    // logsoft [B,V]

    float *ah_p, *attres_p, *nexth_p, *sums_p, *score1_p;
    cudaGetSymbolAddress((void**)&ah_p,     g_ah);
    cudaGetSymbolAddress((void**)&attres_p, g_attres);
    cudaGetSymbolAddress((void**)&nexth_p,  g_nexth);
    cudaGetSymbolAddress((void**)&sums_p,   g_sums);
    cudaGetSymbolAddress((void**)&score1_p, g_score1);

    __nv_bfloat16 *Wa2a_h, *Wa2a_l, *Wa2a1_h, *Wa2a1_l, *Wi_h, *Wi_l, *Wh_h, *Wh_l, *Wah_h, *Wah_l, *Wp_h, *Wp_l;
    cudaGetSymbolAddress((void**)&Wa2a_h,  g_Wa2a_h);  cudaGetSymbolAddress((void**)&Wa2a_l,  g_Wa2a_l);
    cudaGetSymbolAddress((void**)&Wa2a1_h, g_Wa2a1_h); cudaGetSymbolAddress((void**)&Wa2a1_l, g_Wa2a1_l);
    cudaGetSymbolAddress((void**)&Wi_h,    g_Wi_h);    cudaGetSymbolAddress((void**)&Wi_l,    g_Wi_l);
    cudaGetSymbolAddress((void**)&Wh_h,    g_Wh_h);    cudaGetSymbolAddress((void**)&Wh_l,    g_Wh_l);
    cudaGetSymbolAddress((void**)&Wah_h,   g_Wah_h);   cudaGetSymbolAddress((void**)&Wah_l,   g_Wah_l);
    cudaGetSymbolAddress((void**)&Wp_h,    g_Wp_h);    cudaGetSymbolAddress((void**)&Wp_l,    g_Wp_l);

    cudaFuncSetAttribute(attend_dual, cudaFuncAttributeMaxDynamicSharedMemorySize, SMEM_DUAL);
    cudaFuncSetAttribute(tc_gemm,     cudaFuncAttributeMaxDynamicSharedMemorySize, SMEM_GEMM);

    const dim3 blk(256);

    // ---- all weight conversions + gate bias in one launch ----
    conv_all<<<CONV_BLOCKS, blk>>>(W_a2a, W_a2a1, W_i2h, W_h2h, W_a2h, W_proj,
                                   b_i2h, b_h2h, b_a2h);

    // ---- ah0 + fused dual attend GEMM ----
    sgemm_bias<<<dim3((A_ + 63) / 64, (B_ + 63) / 64), blk>>>(prev_h, W_h2a, b_h2a, ah_p, B_, A_, R_);
    attend_dual<<<dim3(4, (B_ * A_) / 128), blk, SMEM_DUAL>>>(
        att, Wa2a_h, Wa2a_l, Wa2a1_h, Wa2a1_l, b_a2a, W_d2d);
    attend_apply<<<B_, 512>>>(att, attres_p, b_d2d, nullptr);

    // ---- LSTM gates (3 phases in grid.z) + cell ----
    tc_gemm<<<dim3(16, 2, 3), blk, SMEM_GEMM>>>(
        x, prev_h, attres_p,
        Wi_h, Wi_l, Wh_h, Wh_l, Wah_h, Wah_l,
        4 * R_, sums_p, 4 * R_, (size_t)B_ * 4 * R_);
    lstm_cell<<<(B_ * R_ / 4 + 255) / 256, blk>>>(prev_c, out_c);

    // ---- attend #1 finish (cheap) ----
    sgemm_bias<<<dim3((A_ + 63) / 64, (B_ + 63) / 64), blk>>>(nexth_p, W_h2a1, b_h2a1, ah_p, B_, A_, R_);
    attend1_score<<<(B_ * A_ * 32 + 255) / 256, blk>>>(b_a2a1, W_d2d1, b_d2d1);
    attend_apply<<<B_, 512>>>(att, attres_p, nullptr, score1_p);

    // ---- top_h, projection, log_softmax ----
    add_toph<<<(B_ * R_ + 255) / 256, blk>>>(out_h);
    tc_gemm<<<dim3((V_ + 127) / 128, 2, 1), blk, SMEM_GEMM>>>(
        out_h, nullptr, nullptr,
        Wp_h, Wp_l, nullptr, nullptr, nullptr, nullptr,
        V_, out_l, V_, 0);
    log_softmax_kernel<<<B_, 512>>>(out_l, b_proj);
}

// round 16
// speedup vs baseline: 1.4804x; 1.0047x over previous
#include <cuda_runtime.h>
#include <cuda_bf16.h>
#include <mma.h>
#include <cstdint>

using namespace nvcuda;

#define B_ 256
#define I_ 512
#define R_ 512
#define A_ 196
#define V_ 10000

// ================= scratch (static device; no allocation allowed) =================
__device__ float g_ah[B_ * A_];            // [B, A]
__device__ float g_spart[B_ * A_ * 4];     // attend0 score partials (2 nblocks x 2 halves)
__device__ float g_score1[B_ * A_];        // attend1 scores
__device__ float g_av1[B_ * A_ * 256];     // raw att.Wa2a1^T (padded N=256), 51.4MB
__device__ float g_attres[B_ * R_];        // [B, R]
__device__ float g_sums[3][B_ * 4 * R_];   // per-phase gate GEMM results
__device__ float g_nexth[B_ * R_];         // [B, R]
__device__ float g_bias[4 * R_];           // combined gate bias

// split-bf16 weight caches
__device__ __nv_bfloat16 g_Wa2a_h[A_ * R_],  g_Wa2a_l[A_ * R_];
__device__ __nv_bfloat16 g_Wa2a1_h[A_ * R_], g_Wa2a1_l[A_ * R_];
__device__ __nv_bfloat16 g_Wi_h[4 * R_ * I_], g_Wi_l[4 * R_ * I_];
__device__ __nv_bfloat16 g_Wh_h[4 * R_ * R_], g_Wh_l[4 * R_ * R_];
__device__ __nv_bfloat16 g_Wah_h[4 * R_ * R_], g_Wah_l[4 * R_ * R_];
__device__ __nv_bfloat16 g_Wp_h[V_ * R_], g_Wp_l[V_ * R_];

// smem staging (bf16 elems, ld = 40); tile = 128x32 = 5120 elems
// A single-buffered, B double-buffered (cp.async)
#define LDT 40
#define OFF_AH  0
#define OFF_AL  5120
#define OFF_B0H 10240
#define OFF_B0L 15360
#define OFF_B1H 20480
#define OFF_B1L 25600
#define SMEM_GEMM 61440
#define SMEM_DUAL 69632   // max(staging 61440, 128x132 fp32 C tile 67584)

// pack 16 floats -> 2x uint4 hi + 2x uint4 lo (8 bf16 per uint4)
__device__ __forceinline__ void split16(const float* f, uint4* H, uint4* L) {
    __align__(16) unsigned short hs[16];
    __align__(16) unsigned short ls[16];
#pragma unroll
    for (int e = 0; e < 16; e++) {
        __nv_bfloat16 h = __float2bfloat16_rn(f[e]);
        hs[e] = __bfloat16_as_ushort(h);
        ls[e] = __bfloat16_as_ushort(__float2bfloat16_rn(f[e] - __bfloat162float(h)));
    }
    H[0] = ((uint4*)hs)[0]; H[1] = ((uint4*)hs)[1];
    L[0] = ((uint4*)ls)[0]; L[1] = ((uint4*)ls)[1];
}

__device__ __forceinline__ uint32_t smem_u32(const void* p) {
    uint32_t a;
    asm("{ .reg .u64 t; cvta.to.shared.u64 t, %1; cvt.u32.u64 %0, t; }" : "=r"(a) : "l"(p));
    return a;
}
// cp.async 16B with zero-fill when src_sz == 0
__device__ __forceinline__ void cp16(uint32_t dst, const void* src, int src_sz) {
    asm volatile("cp.async.cg.shared.global [%0], [%1], 16, %2;"
                 :: "r"(dst), "l"(src), "r"(src_sz));
}
__device__ __forceinline__ void cp_commit() { asm volatile("cp.async.commit_group;"); }
__device__ __forceinline__ void cp_wait1() { asm volatile("cp.async.wait_group 1;"); }
__device__ __forceinline__ void cp_wait0() { asm volatile("cp.async.wait_group 0;"); }

// ---- shared MMA inner step over staged tiles ----
__device__ __forceinline__ void mma_tiles(
    const __nv_bfloat16* sAH, const __nv_bfloat16* sAL,
    const __nv_bfloat16* sBH, const __nv_bfloat16* sBL,
    int wm, int wn, wmma::fragment<wmma::accumulator, 16, 16, 16, float> acc[4][2])
{
#pragma unroll
    for (int ks = 0; ks < 2; ks++) {
        wmma::fragment<wmma::matrix_a, 16, 16, 16, __nv_bfloat16, wmma::row_major> fah[4], fal[4];
#pragma unroll
        for (int i = 0; i < 4; i++) {
            wmma::load_matrix_sync(fah[i], sAH + (wm * 64 + i * 16) * LDT + ks * 16, LDT);
            wmma::load_matrix_sync(fal[i], sAL + (wm * 64 + i * 16) * LDT + ks * 16, LDT);
        }
#pragma unroll
        for (int j = 0; j < 2; j++) {
            wmma::fragment<wmma::matrix_b, 16, 16, 16, __nv_bfloat16, wmma::col_major> fbh, fbl;
            wmma::load_matrix_sync(fbh, sBH + (wn * 32 + j * 16) * LDT + ks * 16, LDT);
            wmma::load_matrix_sync(fbl, sBL + (wn * 32 + j * 16) * LDT + ks * 16, LDT);
#pragma unroll
            for (int i = 0; i < 4; i++) {
                wmma::mma_sync(acc[i][j], fah[i], fbh, acc[i][j]);
                wmma::mma_sync(acc[i][j], fah[i], fbl, acc[i][j]);
                wmma::mma_sync(acc[i][j], fal[i], fbh, acc[i][j]);
            }
        }
    }
}

// ================= fused dual-attend GEMM (round-9 winner, unchanged) =================
// grid (4, BA/128). bx 0,1: C0 = att.Wa2a^T -> tanh/Wd epilogue -> g_spart.
// bx 2,3: C1 = att.Wa2a1^T -> raw store to g_av1 (ld 256).
__global__ void __launch_bounds__(256) attend_dual(
    const float* __restrict__ att,
    const __nv_bfloat16* __restrict__ W0h, const __nv_bfloat16* __restrict__ W0l,
    const __nv_bfloat16* __restrict__ W1h, const __nv_bfloat16* __restrict__ W1l,
    const float* __restrict__ ba0, const float* __restrict__ Wd0)
{
    extern __shared__ char smem[];
    __nv_bfloat16* sAH = (__nv_bfloat16*)smem + OFF_AH;
    __nv_bfloat16* sAL = (__nv_bfloat16*)smem + OFF_AL;

    const int tid = threadIdx.x;
    const int wid = tid >> 5;
    const int wm = wid >> 2, wn = wid & 3;
    const int bx = blockIdx.x;
    const int m0 = blockIdx.y * 128;
    const bool second = (bx >= 2);
    const int n0 = (bx & 1) * 128;
    const __nv_bfloat16* Bh = second ? W1h : W0h;
    const __nv_bfloat16* Bl = second ? W1l : W0l;

    wmma::fragment<wmma::accumulator, 16, 16, 16, float> acc[4][2];
#pragma unroll
    for (int i = 0; i < 4; i++)
#pragma unroll
        for (int j = 0; j < 2; j++) wmma::fill_fragment(acc[i][j], 0.0f);

    const int r  = tid >> 1;
    const int ch = (tid & 1) * 16;
    const int Brow = n0 + r;
    const bool bvalid = (Brow < A_);
    const int BrowC = bvalid ? Brow : 0;
    const int psz = bvalid ? 16 : 0;

    const uint32_t sbase = smem_u32(smem);
    const uint32_t rowoff = (uint32_t)(r * LDT + ch) * 2;
    const uint32_t dBH[2] = { sbase + OFF_B0H * 2 + rowoff, sbase + OFF_B1H * 2 + rowoff };
    const uint32_t dBL[2] = { sbase + OFF_B0L * 2 + rowoff, sbase + OFF_B1L * 2 + rowoff };

    // prologue: B chunk 0 -> buf 0
    {
        const __nv_bfloat16* ph = Bh + (size_t)BrowC * 512 + ch;
        const __nv_bfloat16* pl = Bl + (size_t)BrowC * 512 + ch;
        cp16(dBH[0], ph, psz); cp16(dBH[0] + 16, ph + 8, psz);
        cp16(dBL[0], pl, psz); cp16(dBL[0] + 16, pl + 8, psz);
        cp_commit();
    }

    for (int kc = 0; kc < 16; kc++) {
        __syncthreads();   // prev MMA done: A buf + B[next] buf free
        // ---- A: fp32 -> split bf16 ----
        {
            __align__(16) float f[16];
            const float4* src = (const float4*)(att + (size_t)(m0 + r) * 512 + kc * 32 + ch);
            ((float4*)f)[0] = src[0]; ((float4*)f)[1] = src[1];
            ((float4*)f)[2] = src[2]; ((float4*)f)[3] = src[3];
            uint4 H[2], L[2];
            split16(f, H, L);
            *(uint4*)(sAH + r * LDT + ch)     = H[0];
            *(uint4*)(sAH + r * LDT + ch + 8) = H[1];
            *(uint4*)(sAL + r * LDT + ch)     = L[0];
            *(uint4*)(sAL + r * LDT + ch + 8) = L[1];
        }
        // ---- B: cp.async next chunk into other buffer ----
        if (kc < 15) {
            const int k0 = (kc + 1) * 32;
            const int buf = (kc + 1) & 1;
            const __nv_bfloat16* ph = Bh + (size_t)BrowC * 512 + k0 + ch;
            const __nv_bfloat16* pl = Bl + (size_t)BrowC * 512 + k0 + ch;
            cp16(dBH[buf], ph, psz); cp16(dBH[buf] + 16, ph + 8, psz);
            cp16(dBL[buf], pl, psz); cp16(dBL[buf] + 16, pl + 8, psz);
            cp_commit();
            cp_wait1();
        } else {
            cp_wait0();
        }
        __syncthreads();
        const __nv_bfloat16* sBH = (__nv_bfloat16*)smem + ((kc & 1) ? OFF_B1H : OFF_B0H);
        const __nv_bfloat16* sBL = (__nv_bfloat16*)smem + ((kc & 1) ? OFF_B1L : OFF_B0L);
        mma_tiles(sAH, sAL, sBH, sBL, wm, wn, acc);
    }

    if (second) {
        float* outz = g_av1 + (size_t)m0 * 256;
#pragma unroll
        for (int i = 0; i < 4; i++)
#pragma unroll
            for (int j = 0; j < 2; j++)
                wmma::store_matrix_sync(outz + (size_t)(wm * 64 + i * 16) * 256 + n0 + wn * 32 + j * 16,
                                        acc[i][j], 256, wmma::mem_row_major);
    } else {
        __syncthreads();
        float* Cs = (float*)smem;   // [128][132]
#pragma unroll
        for (int i = 0; i < 4; i++)
#pragma unroll
            for (int j = 0; j < 2; j++)
                wmma::store_matrix_sync(Cs + (wm * 64 + i * 16) * 132 + wn * 32 + j * 16,
                                        acc[i][j], 132, wmma::mem_row_major);
        __syncthreads();
        const int half = tid & 1;
        const int c0 = half * 64;
        float ahm = g_ah[m0 + r];
        float p = 0.f;
#pragma unroll 4
        for (int c = 0; c < 64; c++) {
            int o = n0 + c0 + c;
            if (o < A_)
                p += tanhf(Cs[r * 132 + c0 + c] + ba0[o] + ahm) * Wd0[o];
        }
        g_spart[(size_t)(m0 + r) * 4 + bx * 2 + half] = p;
    }
}

// ================= attend1 finish: scores from stored av1 =================
__global__ void attend1_score(const float* __restrict__ ba, const float* __restrict__ Wd,
                              const float* __restrict__ bd)
{
    const int w = (blockIdx.x * blockDim.x + threadIdx.x) >> 5;   // global warp = row
    const int lane = threadIdx.x & 31;
    if (w >= B_ * A_) return;
    const float* row = g_av1 + (size_t)w * 256;
    float ahm = g_ah[w];
    float p = 0.f;
#pragma unroll
    for (int it = 0; it < 7; it++) {
        int o = it * 32 + lane;
        if (o < A_) p += tanhf(row[o] + ba[o] + ahm) * Wd[o];
    }
#pragma unroll
    for (int off = 16; off > 0; off >>= 1)
        p += __shfl_down_sync(0xffffffff, p, off);
    if (lane == 0) g_score1[w] = p + bd[0];
}

// ================= gates / proj GEMM (round-9 winner, unchanged) =================
__global__ void __launch_bounds__(256, 2) tc_gemm(
    const float* __restrict__ A0, const float* __restrict__ A1, const float* __restrict__ A2,
    const __nv_bfloat16* __restrict__ Bh0, const __nv_bfloat16* __restrict__ Bl0,
    const __nv_bfloat16* __restrict__ Bh1, const __nv_bfloat16* __restrict__ Bl1,
    const __nv_bfloat16* __restrict__ Bh2, const __nv_bfloat16* __restrict__ Bl2,
    int Ntot, float* __restrict__ out, int ldout, size_t zstride)
{
    extern __shared__ char smem[];
    __nv_bfloat16* sAH = (__nv_bfloat16*)smem + OFF_AH;
    __nv_bfloat16* sAL = (__nv_bfloat16*)smem + OFF_AL;

    const int tid = threadIdx.x;
    const int wid = tid >> 5;
    const int wm = wid >> 2, wn = wid & 3;
    const int m0 = blockIdx.y * 128, n0 = blockIdx.x * 128;
    const int z = blockIdx.z;

    const float* Ap = (z == 0) ? A0 : (z == 1) ? A1 : A2;
    const __nv_bfloat16* Bh = (z == 0) ? Bh0 : (z == 1) ? Bh1 : Bh2;
    const __nv_bfloat16* Bl = (z == 0) ? Bl0 : (z == 1) ? Bl1 : Bl2;

    wmma::fragment<wmma::accumulator, 16, 16, 16, float> acc[4][2];
#pragma unroll
    for (int i = 0; i < 4; i++)
#pragma unroll
        for (int j = 0; j < 2; j++) wmma::fill_fragment(acc[i][j], 0.0f);

    const int r  = tid >> 1;
    const int ch = (tid & 1) * 16;
    const int Brow = n0 + r;
    const bool bvalid = (Brow < Ntot);
    const int BrowC = bvalid ? Brow : 0;
    const int psz = bvalid ? 16 : 0;

    const uint32_t sbase = smem_u32(smem);
    const uint32_t rowoff = (uint32_t)(r * LDT + ch) * 2;
    const uint32_t dBH[2] = { sbase + OFF_B0H * 2 + rowoff, sbase + OFF_B1H * 2 + rowoff };
    const uint32_t dBL[2] = { sbase + OFF_B0L * 2 + rowoff, sbase + OFF_B1L * 2 + rowoff };

    {
        const __nv_bfloat16* ph = Bh + (size_t)BrowC * 512 + ch;
        const __nv_bfloat16* pl = Bl + (size_t)BrowC * 512 + ch;
        cp16(dBH[0], ph, psz); cp16(dBH[0] + 16, ph + 8, psz);
        cp16(dBL[0], pl, psz); cp16(dBL[0] + 16, pl + 8, psz);
        cp_commit();
    }

    for (int kc = 0; kc < 16; kc++) {
        __syncthreads();
        {
            __align__(16) float f[16];
            const float4* src = (const float4*)(Ap + (size_t)(m0 + r) * 512 + kc * 32 + ch);
            ((float4*)f)[0] = src[0]; ((float4*)f)[1] = src[1];
            ((float4*)f)[2] = src[2]; ((float4*)f)[3] = src[3];
            uint4 H[2], L[2];
            split16(f, H, L);
            *(uint4*)(sAH + r * LDT + ch)     = H[0];
            *(uint4*)(sAH + r * LDT + ch + 8) = H[1];
            *(uint4*)(sAL + r * LDT + ch)     = L[0];
            *(uint4*)(sAL + r * LDT + ch + 8) = L[1];
        }
        if (kc < 15) {
            const int k0 = (kc + 1) * 32;
            const int buf = (kc + 1) & 1;
            const __nv_bfloat16* ph = Bh + (size_t)BrowC * 512 + k0 + ch;
            const __nv_bfloat16* pl = Bl + (size_t)BrowC * 512 + k0 + ch;
            cp16(dBH[buf], ph, psz); cp16(dBH[buf] + 16, ph + 8, psz);
            cp16(dBL[buf], pl, psz); cp16(dBL[buf] + 16, pl + 8, psz);
            cp_commit();
            cp_wait1();
        } else {
            cp_wait0();
        }
        __syncthreads();
        const __nv_bfloat16* sBH = (__nv_bfloat16*)smem + ((kc & 1) ? OFF_B1H : OFF_B0H);
        const __nv_bfloat16* sBL = (__nv_bfloat16*)smem + ((kc & 1) ? OFF_B1L : OFF_B0L);
        mma_tiles(sAH, sAL, sBH, sBL, wm, wn, acc);
    }

    float* outz = out + (size_t)z * zstride;
#pragma unroll
    for (int i = 0; i < 4; i++) {
        int mrow = m0 + wm * 64 + i * 16;
#pragma unroll
        for (int j = 0; j < 2; j++) {
            int ncol = n0 + wn * 32 + j * 16;
            if (ncol + 16 <= Ntot)
                wmma::store_matrix_sync(outz + (size_t)mrow * ldout + ncol, acc[i][j],
                                        ldout, wmma::mem_row_major);
        }
    }
}

// ================= fused conversion: all weights + gate bias in ONE launch =================
#define C_A2A   (A_ * R_ / 4)
#define C_BIG   (4 * R_ * R_ / 4)
#define C_PROJ  (V_ * R_ / 4)
#define SEG0 0
#define SEG1 (SEG0 + C_A2A)
#define SEG2 (SEG1 + C_A2A)
#define SEG3 (SEG2 + C_BIG)
#define SEG4 (SEG3 + C_BIG)
#define SEG5 (SEG4 + C_BIG)
#define SEG6 (SEG5 + C_PROJ)
#define SEG7 (SEG6 + (4 * R_ / 4))
#define CONV_BLOCKS (SEG7 / 256)

__device__ __forceinline__ void conv_one(const float* __restrict__ src,
                                         __nv_bfloat16* __restrict__ hi,
                                         __nv_bfloat16* __restrict__ lo, int i)
{
    float4 v = ((const float4*)src)[i];
    __nv_bfloat16 hx = __float2bfloat16_rn(v.x), hy = __float2bfloat16_rn(v.y);
    __nv_bfloat16 hz = __float2bfloat16_rn(v.z), hw = __float2bfloat16_rn(v.w);
    __nv_bfloat16 lx = __float2bfloat16_rn(v.x - __bfloat162float(hx));
    __nv_bfloat16 ly = __float2bfloat16_rn(v.y - __bfloat162float(hy));
    __nv_bfloat16 lz = __float2bfloat16_rn(v.z - __bfloat162float(hz));
    __nv_bfloat16 lw = __float2bfloat16_rn(v.w - __bfloat162float(hw));
    uint2 H, L;
    H.x = (uint32_t)__bfloat16_as_ushort(hx) | ((uint32_t)__bfloat16_as_ushort(hy) << 16);
    H.y = (uint32_t)__bfloat16_as_ushort(hz) | ((uint32_t)__bfloat16_as_ushort(hw) << 16);
    L.x = (uint32_t)__bfloat16_as_ushort(lx) | ((uint32_t)__bfloat16_as_ushort(ly) << 16);
    L.y = (uint32_t)__bfloat16_as_ushort(lz) | ((uint32_t)__bfloat16_as_ushort(lw) << 16);
    ((uint2*)hi)[i] = H;
    ((uint2*)lo)[i] = L;
}

__global__ void conv_all(
    const float* __restrict__ W_a2a, const float* __restrict__ W_a2a1,
    const float* __restrict__ W_i2h, const float* __restrict__ W_h2h,
    const float* __restrict__ W_a2h, const float* __restrict__ W_proj,
    const float* __restrict__ b1, const float* __restrict__ b2, const float* __restrict__ b3)
{
    int i = blockIdx.x * 256 + threadIdx.x;
    if (i < SEG1)      conv_one(W_a2a,  g_Wa2a_h,  g_Wa2a_l,  i - SEG0);
    else if (i < SEG2) conv_one(W_a2a1, g_Wa2a1_h, g_Wa2a1_l, i - SEG1);
    else if (i < SEG3) conv_one(W_i2h,  g_Wi_h,    g_Wi_l,    i - SEG2);
    else if (i < SEG4) conv_one(W_h2h,  g_Wh_h,    g_Wh_l,    i - SEG3);
    else if (i < SEG5) conv_one(W_a2h,  g_Wah_h,   g_Wah_l,   i - SEG4);
    else if (i < SEG6) conv_one(W_proj, g_Wp_h,    g_Wp_l,    i - SEG5);
    else if (i < SEG7) {
        int k = i - SEG6;
        float4 v1 = ((const float4*)b1)[k];
        float4 v2 = ((const float4*)b2)[k];
        float4 v3 = ((const float4*)b3)[k];
        float4 o;
        o.x = v1.x + v2.x + v3.x; o.y = v1.y + v2.y + v3.y;
        o.z = v1.z + v2.z + v3.z; o.w = v1.w + v2.w + v3.w;
        ((float4*)g_bias)[k] = o;
    }
}

// ================= SIMT sgemm for the small ah projection =================
__global__ void __launch_bounds__(256, 2) sgemm_bias(
    const float* __restrict__ Am, const float* __restrict__ Bm,
    const float* __restrict__ b1,
    float* __restrict__ C, int M, int N, int K)
{
    __shared__ __align__(16) float As[16][68];
    __shared__ __align__(16) float Bs[16][68];
    const int m0 = blockIdx.y * 64, n0 = blockIdx.x * 64;
    const int tid = threadIdx.x;
    const int tn = tid & 15, tm = tid >> 4;
    const int lrow = tid >> 2, lc = (tid & 3) << 2;

    float acc[4][4] = {};
    for (int k0 = 0; k0 < K; k0 += 16) {
        float4 av = make_float4(0.f, 0.f, 0.f, 0.f);
        float4 bv = make_float4(0.f, 0.f, 0.f, 0.f);
        if (m0 + lrow < M) av = *(const float4*)(Am + (size_t)(m0 + lrow) * K + k0 + lc);
        if (n0 + lrow < N) bv = *(const float4*)(Bm + (size_t)(n0 + lrow) * K + k0 + lc);
        __syncthreads();
        As[lc + 0][lrow] = av.x; As[lc + 1][lrow] = av.y; As[lc + 2][lrow] = av.z; As[lc + 3][lrow] = av.w;
        Bs[lc + 0][lrow] = bv.x; Bs[lc + 1][lrow] = bv.y; Bs[lc + 2][lrow] = bv.z; Bs[lc + 3][lrow] = bv.w;
        __syncthreads();
#pragma unroll
        for (int kk = 0; kk < 16; kk++) {
            float a[4], b[4];
            *(float4*)a = *(const float4*)&As[kk][tm << 2];
            *(float4*)b = *(const float4*)&Bs[kk][tn << 2];
#pragma unroll
            for (int i = 0; i < 4; i++)
#pragma unroll
                for (int j = 0; j < 4; j++)
                    acc[i][j] += a[i] * b[j];
        }
    }
#pragma unroll
    for (int j = 0; j < 4; j++) {
        int n = n0 + (tn << 2) + j;
        if (n >= N) continue;
        float bias = b1 ? b1[n] : 0.f;
#pragma unroll
        for (int i = 0; i < 4; i++) {
            int m = m0 + (tm << 2) + i;
            if (m < M) C[(size_t)m * N + n] = acc[i][j] + bias;
        }
    }
}

// ================= softmax over a + weighted sum of att rows (1024 threads) =================
// threads: 128 R-segments x 8 a-groups (strided a = aq, aq+8, ...)
__global__ void __launch_bounds__(1024) attend_apply(
    const float* __restrict__ att, float* __restrict__ outres,
    const float* __restrict__ bd, const float* __restrict__ scores)
{
    const int b = blockIdx.x, tid = threadIdx.x;  // 1024 threads
    __shared__ float w[A_];
    __shared__ float rbuf[1024];
    __shared__ __align__(16) float4 part[7][128];

    float s = -1e30f;
    if (tid < A_) {
        if (scores) {
            s = scores[b * A_ + tid];
        } else {
            const float* p = &g_spart[(size_t)(b * A_ + tid) * 4];
            s = bd[0] + p[0] + p[1] + p[2] + p[3];
        }
    }
    rbuf[tid] = s;
    __syncthreads();
    for (int off = 512; off > 0; off >>= 1) {
        if (tid < off) rbuf[tid] = fmaxf(rbuf[tid], rbuf[tid + off]);
        __syncthreads();
    }
    float mx = rbuf[0];
    __syncthreads();
    float e = (tid < A_) ? __expf(s - mx) : 0.f;
    rbuf[tid] = e;
    __syncthreads();
    for (int off = 512; off > 0; off >>= 1) {
        if (tid < off) rbuf[tid] += rbuf[tid + off];
        __syncthreads();
    }
    float inv = 1.f / rbuf[0];
    if (tid < A_) w[tid] = e * inv;
    __syncthreads();

    // weighted sum: 128 R-segments x 8 strided a-groups
    const int rseg = tid & 127, aq = tid >> 7;
    const float* ab = att + (size_t)b * A_ * R_ + rseg * 4;
    float4 acc = make_float4(0.f, 0.f, 0.f, 0.f);
#pragma unroll 5
    for (int a = aq; a < A_; a += 8) {
        float4 v = *(const float4*)(ab + (size_t)a * R_);
        float wa = w[a];
        acc.x += v.x * wa; acc.y += v.y * wa;
        acc.z += v.z * wa; acc.w += v.w * wa;
    }
    if (aq > 0) part[aq - 1][rseg] = acc;
    __syncthreads();
    if (aq == 0) {
#pragma unroll
        for (int p = 0; p < 7; p++) {
            float4 v = part[p][rseg];
            acc.x += v.x; acc.y += v.y; acc.z += v.z; acc.w += v.w;
        }
        *(float4*)(outres + (size_t)b * R_ + rseg * 4) = acc;
    }
}

// ================= LSTM cell (float4, sums 3 phase slabs + bias) =================
__global__ void lstm_cell(const float* __restrict__ prev_c, float* __restrict__ out_c)
{
    int idx = blockIdx.x * 256 + threadIdx.x;     // over B*R/4
    if (idx >= B_ * R_ / 4) return;
    int b = idx >> 7;                  // R_/4 = 128
    int j4 = (idx & 127) * 4;
    const size_t base = (size_t)b * 4 * R_;

    float4 sv[4];
#pragma unroll
    for (int g = 0; g < 4; g++) {
        size_t o = base + g * R_ + j4;
        float4 v0 = *(const float4*)&g_sums[0][o];
        float4 v1 = *(const float4*)&g_sums[1][o];
        float4 v2 = *(const float4*)&g_sums[2][o];
        float4 bb = *(const float4*)&g_bias[g * R_ + j4];
        sv[g].x = v0.x + v1.x + v2.x + bb.x;
        sv[g].y = v0.y + v1.y + v2.y + bb.y;
        sv[g].z = v0.z + v1.z + v2.z + bb.z;
        sv[g].w = v0.w + v1.w + v2.w + bb.w;
    }
    float4 pc = *(const float4*)(prev_c + (size_t)b * R_ + j4);
    float4 oc, oh;
#pragma unroll
    for (int e = 0; e < 4; e++) {
        float s0 = (&sv[0].x)[e], s1 = (&sv[1].x)[e], s2 = (&sv[2].x)[e], s3 = (&sv[3].x)[e];
        float ig = 1.f / (1.f + __expf(-s0));
        float fg = 1.f / (1.f + __expf(-s1));
        float og = 1.f / (1.f + __expf(-s2));
        float gt = tanhf(s3);
        float c = fg * (&pc.x)[e] + ig * gt;
        (&oc.x)[e] = c;
        (&oh.x)[e] = og * tanhf(c);
    }
    *(float4*)(out_c + (size_t)b * R_ + j4) = oc;
    *(float4*)(g_nexth + (size_t)b * R_ + j4) = oh;
}

__global__ void add_toph(float* __restrict__ out_h)
{
    int idx = blockIdx.x * 256 + threadIdx.x;
    if (idx >= B_ * R_) return;
    out_h[idx] = g_attres[idx] + g_nexth[idx];
}

// ================= log_softmax: online (max,sum) pass + write pass =================
__global__ void log_softmax_kernel(float* __restrict__ logits, const float* __restrict__ bias)
{
    const int b = blockIdx.x, tid = threadIdx.x;  // 512 threads
    float* row = logits + (size_t)b * V_;
    __shared__ float rm[512], rd[512];

    float m = -1e30f, d = 0.f;
    for (int i = tid; i < V_; i += 512) {
        float v = row[i] + bias[i];
        if (v > m) { d = d * __expf(m - v) + 1.f; m = v; }
        else d += __expf(v - m);
    }
    rm[tid] = m; rd[tid] = d;
    __syncthreads();
    for (int off = 256; off > 0; off >>= 1) {
        if (tid < off) {
            float m2 = rm[tid + off], d2 = rd[tid + off];
            float mo = fmaxf(rm[tid], m2);
            rd[tid] = rd[tid] * __expf(rm[tid] - mo) + d2 * __expf(m2 - mo);
            rm[tid] = mo;
        }
        __syncthreads();
    }
    float lse = rm[0] + logf(rd[0]);
    for (int i = tid; i < V_; i += 512) row[i] = row[i] + bias[i] - lse;
}

// ================= host launch =================
extern "C" void kernel_launch(void* const* d_in, const int* in_sizes, int n_in,
                              void* d_out, int out_size)
{
    const float* x      = (const float*)d_in[0];
    const float* att    = (const float*)d_in[1];
    const float* prev_c = (const float*)d_in[2];
    const float* prev_h = (const float*)d_in[3];
    const float* W_a2a  = (const float*)d_in[4];  const float* b_a2a  = (const float*)d_in[5];
    const float* W_h2a  = (const float*)d_in[6];  const float* b_h2a  = (const float*)d_in[7];
    const float* W_d2d  = (const float*)d_in[8];  const float* b_d2d  = (const float*)d_in[9];
    const float* W_i2h  = (const float*)d_in[10]; const float* b_i2h  = (const float*)d_in[11];
    const float* W_a2h  = (const float*)d_in[12]; const float* b_a2h  = (const float*)d_in[13];
    const float* W_h2h  = (const float*)d_in[14]; const float* b_h2h  = (const float*)d_in[15];
    const float* W_a2a1 = (const float*)d_in[16]; const float* b_a2a1 = (const float*)d_in[17];
    const float* W_h2a1 = (const float*)d_in[18]; const float* b_h2a1 = (const float*)d_in[19];
    const float* W_d2d1 = (const float*)d_in[20]; const float* b_d2d1 = (const float*)d_in[21];
    const float* W_proj = (const float*)d_in[22]; const float* b_proj = (const float*)d_in[23];

    float* out   = (float*)d_out;
    float* out_c = out;                  // next_c  [B,R]
    float* out_h = out + B_ * R_;        // top_h   [B,R]
    float* out_l = out + 2 * B_ * R_;    // logsoft [B,V]

    float *ah_p, *attres_p, *nexth_p, *sums_p, *score1_p;
    cudaGetSymbolAddress((void**)&ah_p,     g_ah);
    cudaGetSymbolAddress((void**)&attres_p, g_attres);
    cudaGetSymbolAddress((void**)&nexth_p,  g_nexth);
    cudaGetSymbolAddress((void**)&sums_p,   g_sums);
    cudaGetSymbolAddress((void**)&score1_p, g_score1);

    __nv_bfloat16 *Wa2a_h, *Wa2a_l, *Wa2a1_h, *Wa2a1_l, *Wi_h, *Wi_l, *Wh_h, *Wh_l, *Wah_h, *Wah_l, *Wp_h, *Wp_l;
    cudaGetSymbolAddress((void**)&Wa2a_h,  g_Wa2a_h);  cudaGetSymbolAddress((void**)&Wa2a_l,  g_Wa2a_l);
    cudaGetSymbolAddress((void**)&Wa2a1_h, g_Wa2a1_h); cudaGetSymbolAddress((void**)&Wa2a1_l, g_Wa2a1_l);
    cudaGetSymbolAddress((void**)&Wi_h,    g_Wi_h);    cudaGetSymbolAddress((void**)&Wi_l,    g_Wi_l);
    cudaGetSymbolAddress((void**)&Wh_h,    g_Wh_h);    cudaGetSymbolAddress((void**)&Wh_l,    g_Wh_l);
    cudaGetSymbolAddress((void**)&Wah_h,   g_Wah_h);   cudaGetSymbolAddress((void**)&Wah_l,   g_Wah_l);
    cudaGetSymbolAddress((void**)&Wp_h,    g_Wp_h);    cudaGetSymbolAddress((void**)&Wp_l,    g_Wp_l);

    cudaFuncSetAttribute(attend_dual, cudaFuncAttributeMaxDynamicSharedMemorySize, SMEM_DUAL);
    cudaFuncSetAttribute(tc_gemm,     cudaFuncAttributeMaxDynamicSharedMemorySize, SMEM_GEMM);

    const dim3 blk(256);

    // ---- all weight conversions + gate bias in one launch ----
    conv_all<<<CONV_BLOCKS, blk>>>(W_a2a, W_a2a1, W_i2h, W_h2h, W_a2h, W_proj,
                                   b_i2h, b_h2h, b_a2h);

    // ---- ah0 + fused dual attend GEMM ----
    sgemm_bias<<<dim3((A_ + 63) / 64, (B_ + 63) / 64), blk>>>(prev_h, W_h2a, b_h2a, ah_p, B_, A_, R_);
    attend_dual<<<dim3(4, (B_ * A_) / 128), blk, SMEM_DUAL>>>(
        att, Wa2a_h, Wa2a_l, Wa2a1_h, Wa2a1_l, b_a2a, W_d2d);
    attend_apply<<<B_, 1024>>>(att, attres_p, b_d2d, nullptr);

    // ---- LSTM gates (3 phases in grid.z) + cell ----
    tc_gemm<<<dim3(16, 2, 3), blk, SMEM_GEMM>>>(
        x, prev_h, attres_p,
        Wi_h, Wi_l, Wh_h, Wh_l, Wah_h, Wah_l,
        4 * R_, sums_p, 4 * R_, (size_t)B_ * 4 * R_);
    lstm_cell<<<(B_ * R_ / 4 + 255) / 256, blk>>>(prev_c, out_c);

    // ---- attend #1 finish (cheap) ----
    sgemm_bias<<<dim3((A_ + 63) / 64, (B_ + 63) / 64), blk>>>(nexth_p, W_h2a1, b_h2a1, ah_p, B_, A_, R_);
    attend1_score<<<(B_ * A_ * 32 + 255) / 256, blk>>>(b_a2a1, W_d2d1, b_d2d1);
    attend_apply<<<B_, 1024>>>(att, attres_p, nullptr, score1_p);

    // ---- top_h, projection, log_softmax ----
    add_toph<<<(B_ * R_ + 255) / 256, blk>>>(out_h);
    tc_gemm<<<dim3((V_ + 127) / 128, 2, 1), blk, SMEM_GEMM>>>(
        out_h, nullptr, nullptr,
        Wp_h, Wp_l, nullptr, nullptr, nullptr, nullptr,
        V_, out_l, V_, 0);
    log_softmax_kernel<<<B_, 512>>>(out_l, b_proj);
}

// round 17
// speedup vs baseline: 1.6118x; 1.0888x over previous
#include <cuda_runtime.h>
#include <cuda_bf16.h>
#include <mma.h>
#include <cstdint>

using namespace nvcuda;

#define B_ 256
#define I_ 512
#define R_ 512
#define A_ 196
#define V_ 10000

// ================= scratch (static device; no allocation allowed) =================
__device__ float g_ah4[4][B_ * A_];        // split-K slabs of h-projection
__device__ float g_spart[B_ * A_ * 4];     // attend0 score partials (2 nblocks x 2 halves)
__device__ float g_score1[B_ * A_];        // attend1 scores
__device__ float g_av1[B_ * A_ * 256];     // raw att.Wa2a1^T (padded N=256), 51.4MB
__device__ float g_attres[B_ * R_];        // [B, R]
__device__ float g_sums[3][B_ * 4 * R_];   // per-phase gate GEMM results
__device__ float g_nexth[B_ * R_];         // [B, R]
__device__ float g_bias[4 * R_];           // combined gate bias

// split-bf16 weight caches
__device__ __nv_bfloat16 g_Wa2a_h[A_ * R_],  g_Wa2a_l[A_ * R_];
__device__ __nv_bfloat16 g_Wa2a1_h[A_ * R_], g_Wa2a1_l[A_ * R_];
__device__ __nv_bfloat16 g_Wi_h[4 * R_ * I_], g_Wi_l[4 * R_ * I_];
__device__ __nv_bfloat16 g_Wh_h[4 * R_ * R_], g_Wh_l[4 * R_ * R_];
__device__ __nv_bfloat16 g_Wah_h[4 * R_ * R_], g_Wah_l[4 * R_ * R_];
__device__ __nv_bfloat16 g_Wp_h[V_ * R_], g_Wp_l[V_ * R_];

// smem staging (bf16 elems, ld = 40); tile = 128x32 = 5120 elems
#define LDT 40
#define OFF_AH  0
#define OFF_AL  5120
#define OFF_B0H 10240
#define OFF_B0L 15360
#define OFF_B1H 20480
#define OFF_B1L 25600
#define SMEM_GEMM 61440
#define SMEM_DUAL 69632   // max(staging 61440, 128x132 fp32 C tile 67584)

// pack 16 floats -> 2x uint4 hi + 2x uint4 lo (8 bf16 per uint4)
__device__ __forceinline__ void split16(const float* f, uint4* H, uint4* L) {
    __align__(16) unsigned short hs[16];
    __align__(16) unsigned short ls[16];
#pragma unroll
    for (int e = 0; e < 16; e++) {
        __nv_bfloat16 h = __float2bfloat16_rn(f[e]);
        hs[e] = __bfloat16_as_ushort(h);
        ls[e] = __bfloat16_as_ushort(__float2bfloat16_rn(f[e] - __bfloat162float(h)));
    }
    H[0] = ((uint4*)hs)[0]; H[1] = ((uint4*)hs)[1];
    L[0] = ((uint4*)ls)[0]; L[1] = ((uint4*)ls)[1];
}

__device__ __forceinline__ uint32_t smem_u32(const void* p) {
    uint32_t a;
    asm("{ .reg .u64 t; cvta.to.shared.u64 t, %1; cvt.u32.u64 %0, t; }" : "=r"(a) : "l"(p));
    return a;
}
// cp.async 16B with zero-fill when src_sz == 0
__device__ __forceinline__ void cp16(uint32_t dst, const void* src, int src_sz) {
    asm volatile("cp.async.cg.shared.global [%0], [%1], 16, %2;"
                 :: "r"(dst), "l"(src), "r"(src_sz));
}
__device__ __forceinline__ void cp_commit() { asm volatile("cp.async.commit_group;"); }
__device__ __forceinline__ void cp_wait1() { asm volatile("cp.async.wait_group 1;"); }
__device__ __forceinline__ void cp_wait0() { asm volatile("cp.async.wait_group 0;"); }

// ---- shared MMA inner step over staged tiles ----
__device__ __forceinline__ void mma_tiles(
    const __nv_bfloat16* sAH, const __nv_bfloat16* sAL,
    const __nv_bfloat16* sBH, const __nv_bfloat16* sBL,
    int wm, int wn, wmma::fragment<wmma::accumulator, 16, 16, 16, float> acc[4][2])
{
#pragma unroll
    for (int ks = 0; ks < 2; ks++) {
        wmma::fragment<wmma::matrix_a, 16, 16, 16, __nv_bfloat16, wmma::row_major> fah[4], fal[4];
#pragma unroll
        for (int i = 0; i < 4; i++) {
            wmma::load_matrix_sync(fah[i], sAH + (wm * 64 + i * 16) * LDT + ks * 16, LDT);
            wmma::load_matrix_sync(fal[i], sAL + (wm * 64 + i * 16) * LDT + ks * 16, LDT);
        }
#pragma unroll
        for (int j = 0; j < 2; j++) {
            wmma::fragment<wmma::matrix_b, 16, 16, 16, __nv_bfloat16, wmma::col_major> fbh, fbl;
            wmma::load_matrix_sync(fbh, sBH + (wn * 32 + j * 16) * LDT + ks * 16, LDT);
            wmma::load_matrix_sync(fbl, sBL + (wn * 32 + j * 16) * LDT + ks * 16, LDT);
#pragma unroll
            for (int i = 0; i < 4; i++) {
                wmma::mma_sync(acc[i][j], fah[i], fbh, acc[i][j]);
                wmma::mma_sync(acc[i][j], fah[i], fbl, acc[i][j]);
                wmma::mma_sync(acc[i][j], fal[i], fbh, acc[i][j]);
            }
        }
    }
}

// ================= fused dual-attend GEMM =================
// grid (4, BA/128). bx 0,1: C0 = att.Wa2a^T -> tanh/Wd epilogue -> g_spart.
// bx 2,3: C1 = att.Wa2a1^T -> raw store to g_av1 (ld 256).
__global__ void __launch_bounds__(256) attend_dual(
    const float* __restrict__ att,
    const __nv_bfloat16* __restrict__ W0h, const __nv_bfloat16* __restrict__ W0l,
    const __nv_bfloat16* __restrict__ W1h, const __nv_bfloat16* __restrict__ W1l,
    const float* __restrict__ ba0, const float* __restrict__ Wd0)
{
    extern __shared__ char smem[];
    __nv_bfloat16* sAH = (__nv_bfloat16*)smem + OFF_AH;
    __nv_bfloat16* sAL = (__nv_bfloat16*)smem + OFF_AL;

    const int tid = threadIdx.x;
    const int wid = tid >> 5;
    const int wm = wid >> 2, wn = wid & 3;
    const int bx = blockIdx.x;
    const int m0 = blockIdx.y * 128;
    const bool second = (bx >= 2);
    const int n0 = (bx & 1) * 128;
    const __nv_bfloat16* Bh = second ? W1h : W0h;
    const __nv_bfloat16* Bl = second ? W1l : W0l;

    wmma::fragment<wmma::accumulator, 16, 16, 16, float> acc[4][2];
#pragma unroll
    for (int i = 0; i < 4; i++)
#pragma unroll
        for (int j = 0; j < 2; j++) wmma::fill_fragment(acc[i][j], 0.0f);

    const int r  = tid >> 1;
    const int ch = (tid & 1) * 16;
    const int Brow = n0 + r;
    const bool bvalid = (Brow < A_);
    const int BrowC = bvalid ? Brow : 0;
    const int psz = bvalid ? 16 : 0;

    const uint32_t sbase = smem_u32(smem);
    const uint32_t rowoff = (uint32_t)(r * LDT + ch) * 2;
    const uint32_t dBH[2] = { sbase + OFF_B0H * 2 + rowoff, sbase + OFF_B1H * 2 + rowoff };
    const uint32_t dBL[2] = { sbase + OFF_B0L * 2 + rowoff, sbase + OFF_B1L * 2 + rowoff };

    // prologue: B chunk 0 -> buf 0
    {
        const __nv_bfloat16* ph = Bh + (size_t)BrowC * 512 + ch;
        const __nv_bfloat16* pl = Bl + (size_t)BrowC * 512 + ch;
        cp16(dBH[0], ph, psz); cp16(dBH[0] + 16, ph + 8, psz);
        cp16(dBL[0], pl, psz); cp16(dBL[0] + 16, pl + 8, psz);
        cp_commit();
    }

    for (int kc = 0; kc < 16; kc++) {
        __syncthreads();   // prev MMA done: A buf + B[next] buf free
        // ---- A: fp32 -> split bf16 ----
        {
            __align__(16) float f[16];
            const float4* src = (const float4*)(att + (size_t)(m0 + r) * 512 + kc * 32 + ch);
            ((float4*)f)[0] = src[0]; ((float4*)f)[1] = src[1];
            ((float4*)f)[2] = src[2]; ((float4*)f)[3] = src[3];
            uint4 H[2], L[2];
            split16(f, H, L);
            *(uint4*)(sAH + r * LDT + ch)     = H[0];
            *(uint4*)(sAH + r * LDT + ch + 8) = H[1];
            *(uint4*)(sAL + r * LDT + ch)     = L[0];
            *(uint4*)(sAL + r * LDT + ch + 8) = L[1];
        }
        // ---- B: cp.async next chunk into other buffer ----
        if (kc < 15) {
            const int k0 = (kc + 1) * 32;
            const int buf = (kc + 1) & 1;
            const __nv_bfloat16* ph = Bh + (size_t)BrowC * 512 + k0 + ch;
            const __nv_bfloat16* pl = Bl + (size_t)BrowC * 512 + k0 + ch;
            cp16(dBH[buf], ph, psz); cp16(dBH[buf] + 16, ph + 8, psz);
            cp16(dBL[buf], pl, psz); cp16(dBL[buf] + 16, pl + 8, psz);
            cp_commit();
            cp_wait1();
        } else {
            cp_wait0();
        }
        __syncthreads();
        const __nv_bfloat16* sBH = (__nv_bfloat16*)smem + ((kc & 1) ? OFF_B1H : OFF_B0H);
        const __nv_bfloat16* sBL = (__nv_bfloat16*)smem + ((kc & 1) ? OFF_B1L : OFF_B0L);
        mma_tiles(sAH, sAL, sBH, sBL, wm, wn, acc);
    }

    if (second) {
        float* outz = g_av1 + (size_t)m0 * 256;
#pragma unroll
        for (int i = 0; i < 4; i++)
#pragma unroll
            for (int j = 0; j < 2; j++)
                wmma::store_matrix_sync(outz + (size_t)(wm * 64 + i * 16) * 256 + n0 + wn * 32 + j * 16,
                                        acc[i][j], 256, wmma::mem_row_major);
    } else {
        __syncthreads();
        float* Cs = (float*)smem;   // [128][132]
#pragma unroll
        for (int i = 0; i < 4; i++)
#pragma unroll
            for (int j = 0; j < 2; j++)
                wmma::store_matrix_sync(Cs + (wm * 64 + i * 16) * 132 + wn * 32 + j * 16,
                                        acc[i][j], 132, wmma::mem_row_major);
        __syncthreads();
        const int half = tid & 1;
        const int c0 = half * 64;
        const int mi = m0 + r;
        float ahm = g_ah4[0][mi] + g_ah4[1][mi] + g_ah4[2][mi] + g_ah4[3][mi];
        float p = 0.f;
#pragma unroll 4
        for (int c = 0; c < 64; c++) {
            int o = n0 + c0 + c;
            if (o < A_)
                p += tanhf(Cs[r * 132 + c0 + c] + ba0[o] + ahm) * Wd0[o];
        }
        g_spart[(size_t)mi * 4 + bx * 2 + half] = p;
    }
}

// ================= attend1 finish: scores from stored av1 (float4) =================
__global__ void attend1_score(const float* __restrict__ ba, const float* __restrict__ Wd,
                              const float* __restrict__ bd)
{
    const int w = (blockIdx.x * blockDim.x + threadIdx.x) >> 5;   // global warp = row
    const int lane = threadIdx.x & 31;
    if (w >= B_ * A_) return;
    const float4* row4 = (const float4*)(g_av1 + (size_t)w * 256);
    const float4* ba4 = (const float4*)ba;
    const float4* wd4 = (const float4*)Wd;
    float ahm = g_ah4[0][w] + g_ah4[1][w] + g_ah4[2][w] + g_ah4[3][w];
    float p = 0.f;
#pragma unroll
    for (int it = 0; it < 2; it++) {
        int idx = it * 32 + lane;             // 49 float4 = 196 floats exactly
        if (idx < 49) {
            float4 v = row4[idx];
            float4 bb = ba4[idx];
            float4 dd = wd4[idx];
            p += tanhf(v.x + bb.x + ahm) * dd.x;
            p += tanhf(v.y + bb.y + ahm) * dd.y;
            p += tanhf(v.z + bb.z + ahm) * dd.z;
            p += tanhf(v.w + bb.w + ahm) * dd.w;
        }
    }
#pragma unroll
    for (int off = 16; off > 0; off >>= 1)
        p += __shfl_down_sync(0xffffffff, p, off);
    if (lane == 0) g_score1[w] = p + bd[0];
}

// ================= gates / proj GEMM (unchanged core) =================
__global__ void __launch_bounds__(256, 2) tc_gemm(
    const float* __restrict__ A0, const float* __restrict__ A1, const float* __restrict__ A2,
    const __nv_bfloat16* __restrict__ Bh0, const __nv_bfloat16* __restrict__ Bl0,
    const __nv_bfloat16* __restrict__ Bh1, const __nv_bfloat16* __restrict__ Bl1,
    const __nv_bfloat16* __restrict__ Bh2, const __nv_bfloat16* __restrict__ Bl2,
    int Ntot, float* __restrict__ out, int ldout, size_t zstride)
{
    extern __shared__ char smem[];
    __nv_bfloat16* sAH = (__nv_bfloat16*)smem + OFF_AH;
    __nv_bfloat16* sAL = (__nv_bfloat16*)smem + OFF_AL;

    const int tid = threadIdx.x;
    const int wid = tid >> 5;
    const int wm = wid >> 2, wn = wid & 3;
    const int m0 = blockIdx.y * 128, n0 = blockIdx.x * 128;
    const int z = blockIdx.z;

    const float* Ap = (z == 0) ? A0 : (z == 1) ? A1 : A2;
    const __nv_bfloat16* Bh = (z == 0) ? Bh0 : (z == 1) ? Bh1 : Bh2;
    const __nv_bfloat16* Bl = (z == 0) ? Bl0 : (z == 1) ? Bl1 : Bl2;

    wmma::fragment<wmma::accumulator, 16, 16, 16, float> acc[4][2];
#pragma unroll
    for (int i = 0; i < 4; i++)
#pragma unroll
        for (int j = 0; j < 2; j++) wmma::fill_fragment(acc[i][j], 0.0f);

    const int r  = tid >> 1;
    const int ch = (tid & 1) * 16;
    const int Brow = n0 + r;
    const bool bvalid = (Brow < Ntot);
    const int BrowC = bvalid ? Brow : 0;
    const int psz = bvalid ? 16 : 0;

    const uint32_t sbase = smem_u32(smem);
    const uint32_t rowoff = (uint32_t)(r * LDT + ch) * 2;
    const uint32_t dBH[2] = { sbase + OFF_B0H * 2 + rowoff, sbase + OFF_B1H * 2 + rowoff };
    const uint32_t dBL[2] = { sbase + OFF_B0L * 2 + rowoff, sbase + OFF_B1L * 2 + rowoff };

    {
        const __nv_bfloat16* ph = Bh + (size_t)BrowC * 512 + ch;
        const __nv_bfloat16* pl = Bl + (size_t)BrowC * 512 + ch;
        cp16(dBH[0], ph, psz); cp16(dBH[0] + 16, ph + 8, psz);
        cp16(dBL[0], pl, psz); cp16(dBL[0] + 16, pl + 8, psz);
        cp_commit();
    }

    for (int kc = 0; kc < 16; kc++) {
        __syncthreads();
        {
            __align__(16) float f[16];
            const float4* src = (const float4*)(Ap + (size_t)(m0 + r) * 512 + kc * 32 + ch);
            ((float4*)f)[0] = src[0]; ((float4*)f)[1] = src[1];
            ((float4*)f)[2] = src[2]; ((float4*)f)[3] = src[3];
            uint4 H[2], L[2];
            split16(f, H, L);
            *(uint4*)(sAH + r * LDT + ch)     = H[0];
            *(uint4*)(sAH + r * LDT + ch + 8) = H[1];
            *(uint4*)(sAL + r * LDT + ch)     = L[0];
            *(uint4*)(sAL + r * LDT + ch + 8) = L[1];
        }
        if (kc < 15) {
            const int k0 = (kc + 1) * 32;
            const int buf = (kc + 1) & 1;
            const __nv_bfloat16* ph = Bh + (size_t)BrowC * 512 + k0 + ch;
            const __nv_bfloat16* pl = Bl + (size_t)BrowC * 512 + k0 + ch;
            cp16(dBH[buf], ph, psz); cp16(dBH[buf] + 16, ph + 8, psz);
            cp16(dBL[buf], pl, psz); cp16(dBL[buf] + 16, pl + 8, psz);
            cp_commit();
            cp_wait1();
        } else {
            cp_wait0();
        }
        __syncthreads();
        const __nv_bfloat16* sBH = (__nv_bfloat16*)smem + ((kc & 1) ? OFF_B1H : OFF_B0H);
        const __nv_bfloat16* sBL = (__nv_bfloat16*)smem + ((kc & 1) ? OFF_B1L : OFF_B0L);
        mma_tiles(sAH, sAL, sBH, sBL, wm, wn, acc);
    }

    float* outz = out + (size_t)z * zstride;
#pragma unroll
    for (int i = 0; i < 4; i++) {
        int mrow = m0 + wm * 64 + i * 16;
#pragma unroll
        for (int j = 0; j < 2; j++) {
            int ncol = n0 + wn * 32 + j * 16;
            if (ncol + 16 <= Ntot)
                wmma::store_matrix_sync(outz + (size_t)mrow * ldout + ncol, acc[i][j],
                                        ldout, wmma::mem_row_major);
        }
    }
}

// ================= fused conversion: all weights + gate bias in ONE launch =================
#define C_A2A   (A_ * R_ / 4)
#define C_BIG   (4 * R_ * R_ / 4)
#define C_PROJ  (V_ * R_ / 4)
#define SEG0 0
#define SEG1 (SEG0 + C_A2A)
#define SEG2 (SEG1 + C_A2A)
#define SEG3 (SEG2 + C_BIG)
#define SEG4 (SEG3 + C_BIG)
#define SEG5 (SEG4 + C_BIG)
#define SEG6 (SEG5 + C_PROJ)
#define SEG7 (SEG6 + (4 * R_ / 4))
#define CONV_BLOCKS (SEG7 / 256)

__device__ __forceinline__ void conv_one(const float* __restrict__ src,
                                         __nv_bfloat16* __restrict__ hi,
                                         __nv_bfloat16* __restrict__ lo, int i)
{
    float4 v = ((const float4*)src)[i];
    __nv_bfloat16 hx = __float2bfloat16_rn(v.x), hy = __float2bfloat16_rn(v.y);
    __nv_bfloat16 hz = __float2bfloat16_rn(v.z), hw = __float2bfloat16_rn(v.w);
    __nv_bfloat16 lx = __float2bfloat16_rn(v.x - __bfloat162float(hx));
    __nv_bfloat16 ly = __float2bfloat16_rn(v.y - __bfloat162float(hy));
    __nv_bfloat16 lz = __float2bfloat16_rn(v.z - __bfloat162float(hz));
    __nv_bfloat16 lw = __float2bfloat16_rn(v.w - __bfloat162float(hw));
    uint2 H, L;
    H.x = (uint32_t)__bfloat16_as_ushort(hx) | ((uint32_t)__bfloat16_as_ushort(hy) << 16);
    H.y = (uint32_t)__bfloat16_as_ushort(hz) | ((uint32_t)__bfloat16_as_ushort(hw) << 16);
    L.x = (uint32_t)__bfloat16_as_ushort(lx) | ((uint32_t)__bfloat16_as_ushort(ly) << 16);
    L.y = (uint32_t)__bfloat16_as_ushort(lz) | ((uint32_t)__bfloat16_as_ushort(lw) << 16);
    ((uint2*)hi)[i] = H;
    ((uint2*)lo)[i] = L;
}

__global__ void conv_all(
    const float* __restrict__ W_a2a, const float* __restrict__ W_a2a1,
    const float* __restrict__ W_i2h, const float* __restrict__ W_h2h,
    const float* __restrict__ W_a2h, const float* __restrict__ W_proj,
    const float* __restrict__ b1, const float* __restrict__ b2, const float* __restrict__ b3)
{
    int i = blockIdx.x * 256 + threadIdx.x;
    if (i < SEG1)      conv_one(W_a2a,  g_Wa2a_h,  g_Wa2a_l,  i - SEG0);
    else if (i < SEG2) conv_one(W_a2a1, g_Wa2a1_h, g_Wa2a1_l, i - SEG1);
    else if (i < SEG3) conv_one(W_i2h,  g_Wi_h,    g_Wi_l,    i - SEG2);
    else if (i < SEG4) conv_one(W_h2h,  g_Wh_h,    g_Wh_l,    i - SEG3);
    else if (i < SEG5) conv_one(W_a2h,  g_Wah_h,   g_Wah_l,   i - SEG4);
    else if (i < SEG6) conv_one(W_proj, g_Wp_h,    g_Wp_l,    i - SEG5);
    else if (i < SEG7) {
        int k = i - SEG6;
        float4 v1 = ((const float4*)b1)[k];
        float4 v2 = ((const float4*)b2)[k];
        float4 v3 = ((const float4*)b3)[k];
        float4 o;
        o.x = v1.x + v2.x + v3.x; o.y = v1.y + v2.y + v3.y;
        o.z = v1.z + v2.z + v3.z; o.w = v1.w + v2.w + v3.w;
        ((float4*)g_bias)[k] = o;
    }
}

// ================= split-K SIMT sgemm for the ah projection =================
// grid (4, 4, 4): 64x64 tiles, K-slab 128 per z. Writes g_ah4[z]; bias added at z==0.
__global__ void __launch_bounds__(256, 2) sgemm_splitk(
    const float* __restrict__ Am, const float* __restrict__ Bm,
    const float* __restrict__ b1, int M, int N)
{
    __shared__ __align__(16) float As[16][68];
    __shared__ __align__(16) float Bs[16][68];
    const int m0 = blockIdx.y * 64, n0 = blockIdx.x * 64;
    const int z = blockIdx.z;
    const int kbase = z * 128;
    const int tid = threadIdx.x;
    const int tn = tid & 15, tm = tid >> 4;
    const int lrow = tid >> 2, lc = (tid & 3) << 2;

    float acc[4][4] = {};
    for (int k0 = kbase; k0 < kbase + 128; k0 += 16) {
        float4 av = make_float4(0.f, 0.f, 0.f, 0.f);
        float4 bv = make_float4(0.f, 0.f, 0.f, 0.f);
        if (m0 + lrow < M) av = *(const float4*)(Am + (size_t)(m0 + lrow) * R_ + k0 + lc);
        if (n0 + lrow < N) bv = *(const float4*)(Bm + (size_t)(n0 + lrow) * R_ + k0 + lc);
        __syncthreads();
        As[lc + 0][lrow] = av.x; As[lc + 1][lrow] = av.y; As[lc + 2][lrow] = av.z; As[lc + 3][lrow] = av.w;
        Bs[lc + 0][lrow] = bv.x; Bs[lc + 1][lrow] = bv.y; Bs[lc + 2][lrow] = bv.z; Bs[lc + 3][lrow] = bv.w;
        __syncthreads();
#pragma unroll
        for (int kk = 0; kk < 16; kk++) {
            float a[4], b[4];
            *(float4*)a = *(const float4*)&As[kk][tm << 2];
            *(float4*)b = *(const float4*)&Bs[kk][tn << 2];
#pragma unroll
            for (int i = 0; i < 4; i++)
#pragma unroll
                for (int j = 0; j < 4; j++)
                    acc[i][j] += a[i] * b[j];
        }
    }
#pragma unroll
    for (int j = 0; j < 4; j++) {
        int n = n0 + (tn << 2) + j;
        if (n >= N) continue;
        float bias = (z == 0 && b1) ? b1[n] : 0.f;
#pragma unroll
        for (int i = 0; i < 4; i++) {
            int m = m0 + (tm << 2) + i;
            if (m < M) g_ah4[z][(size_t)m * N + n] = acc[i][j] + bias;
        }
    }
}

// ================= softmax over a + weighted sum of att rows (1024 threads) =================
__global__ void __launch_bounds__(1024) attend_apply(
    const float* __restrict__ att, float* __restrict__ outres,
    const float* __restrict__ bd, const float* __restrict__ scores)
{
    const int b = blockIdx.x, tid = threadIdx.x;  // 1024 threads
    __shared__ float w[A_];
    __shared__ float rbuf[1024];
    __shared__ __align__(16) float4 part[7][128];

    float s = -1e30f;
    if (tid < A_) {
        if (scores) {
            s = scores[b * A_ + tid];
        } else {
            const float* p = &g_spart[(size_t)(b * A_ + tid) * 4];
            s = bd[0] + p[0] + p[1] + p[2] + p[3];
        }
    }
    rbuf[tid] = s;
    __syncthreads();
    for (int off = 512; off > 0; off >>= 1) {
        if (tid < off) rbuf[tid] = fmaxf(rbuf[tid], rbuf[tid + off]);
        __syncthreads();
    }
    float mx = rbuf[0];
    __syncthreads();
    float e = (tid < A_) ? __expf(s - mx) : 0.f;
    rbuf[tid] = e;
    __syncthreads();
    for (int off = 512; off > 0; off >>= 1) {
        if (tid < off) rbuf[tid] += rbuf[tid + off];
        __syncthreads();
    }
    float inv = 1.f / rbuf[0];
    if (tid < A_) w[tid] = e * inv;
    __syncthreads();

    // weighted sum: 128 R-segments x 8 strided a-groups
    const int rseg = tid & 127, aq = tid >> 7;
    const float* ab = att + (size_t)b * A_ * R_ + rseg * 4;
    float4 acc = make_float4(0.f, 0.f, 0.f, 0.f);
#pragma unroll 5
    for (int a = aq; a < A_; a += 8) {
        float4 v = *(const float4*)(ab + (size_t)a * R_);
        float wa = w[a];
        acc.x += v.x * wa; acc.y += v.y * wa;
        acc.z += v.z * wa; acc.w += v.w * wa;
    }
    if (aq > 0) part[aq - 1][rseg] = acc;
    __syncthreads();
    if (aq == 0) {
#pragma unroll
        for (int p = 0; p < 7; p++) {
            float4 v = part[p][rseg];
            acc.x += v.x; acc.y += v.y; acc.z += v.z; acc.w += v.w;
        }
        *(float4*)(outres + (size_t)b * R_ + rseg * 4) = acc;
    }
}

// ================= LSTM cell (float4, sums 3 phase slabs + bias) =================
__global__ void lstm_cell(const float* __restrict__ prev_c, float* __restrict__ out_c)
{
    int idx = blockIdx.x * 256 + threadIdx.x;     // over B*R/4
    if (idx >= B_ * R_ / 4) return;
    int b = idx >> 7;                  // R_/4 = 128
    int j4 = (idx & 127) * 4;
    const size_t base = (size_t)b * 4 * R_;

    float4 sv[4];
#pragma unroll
    for (int g = 0; g < 4; g++) {
        size_t o = base + g * R_ + j4;
        float4 v0 = *(const float4*)&g_sums[0][o];
        float4 v1 = *(const float4*)&g_sums[1][o];
        float4 v2 = *(const float4*)&g_sums[2][o];
        float4 bb = *(const float4*)&g_bias[g * R_ + j4];
        sv[g].x = v0.x + v1.x + v2.x + bb.x;
        sv[g].y = v0.y + v1.y + v2.y + bb.y;
        sv[g].z = v0.z + v1.z + v2.z + bb.z;
        sv[g].w = v0.w + v1.w + v2.w + bb.w;
    }
    float4 pc = *(const float4*)(prev_c + (size_t)b * R_ + j4);
    float4 oc, oh;
#pragma unroll
    for (int e = 0; e < 4; e++) {
        float s0 = (&sv[0].x)[e], s1 = (&sv[1].x)[e], s2 = (&sv[2].x)[e], s3 = (&sv[3].x)[e];
        float ig = 1.f / (1.f + __expf(-s0));
        float fg = 1.f / (1.f + __expf(-s1));
        float og = 1.f / (1.f + __expf(-s2));
        float gt = tanhf(s3);
        float c = fg * (&pc.x)[e] + ig * gt;
        (&oc.x)[e] = c;
        (&oh.x)[e] = og * tanhf(c);
    }
    *(float4*)(out_c + (size_t)b * R_ + j4) = oc;
    *(float4*)(g_nexth + (size_t)b * R_ + j4) = oh;
}

__global__ void add_toph(float* __restrict__ out_h)
{
    int idx = blockIdx.x * 256 + threadIdx.x;
    if (idx >= B_ * R_) return;
    out_h[idx] = g_attres[idx] + g_nexth[idx];
}

// ================= log_softmax: online (max,sum) pass + write pass =================
__global__ void log_softmax_kernel(float* __restrict__ logits, const float* __restrict__ bias)
{
    const int b = blockIdx.x, tid = threadIdx.x;  // 512 threads
    float* row = logits + (size_t)b * V_;
    __shared__ float rm[512], rd[512];

    float m = -1e30f, d = 0.f;
    for (int i = tid; i < V_; i += 512) {
        float v = row[i] + bias[i];
        if (v > m) { d = d * __expf(m - v) + 1.f; m = v; }
        else d += __expf(v - m);
    }
    rm[tid] = m; rd[tid] = d;
    __syncthreads();
    for (int off = 256; off > 0; off >>= 1) {
        if (tid < off) {
            float m2 = rm[tid + off], d2 = rd[tid + off];
            float mo = fmaxf(rm[tid], m2);
            rd[tid] = rd[tid] * __expf(rm[tid] - mo) + d2 * __expf(m2 - mo);
            rm[tid] = mo;
        }
        __syncthreads();
    }
    float lse = rm[0] + logf(rd[0]);
    for (int i = tid; i < V_; i += 512) row[i] = row[i] + bias[i] - lse;
}

// ================= host launch =================
extern "C" void kernel_launch(void* const* d_in, const int* in_sizes, int n_in,
                              void* d_out, int out_size)
{
    const float* x      = (const float*)d_in[0];
    const float* att    = (const float*)d_in[1];
    const float* prev_c = (const float*)d_in[2];
    const float* prev_h = (const float*)d_in[3];
    const float* W_a2a  = (const float*)d_in[4];  const float* b_a2a  = (const float*)d_in[5];
    const float* W_h2a  = (const float*)d_in[6];  const float* b_h2a  = (const float*)d_in[7];
    const float* W_d2d  = (const float*)d_in[8];  const float* b_d2d  = (const float*)d_in[9];
    const float* W_i2h  = (const float*)d_in[10]; const float* b_i2h  = (const float*)d_in[11];
    const float* W_a2h  = (const float*)d_in[12]; const float* b_a2h  = (const float*)d_in[13];
    const float* W_h2h  = (const float*)d_in[14]; const float* b_h2h  = (const float*)d_in[15];
    const float* W_a2a1 = (const float*)d_in[16]; const float* b_a2a1 = (const float*)d_in[17];
    const float* W_h2a1 = (const float*)d_in[18]; const float* b_h2a1 = (const float*)d_in[19];
    const float* W_d2d1 = (const float*)d_in[20]; const float* b_d2d1 = (const float*)d_in[21];
    const float* W_proj = (const float*)d_in[22]; const float* b_proj = (const float*)d_in[23];

    float* out   = (float*)d_out;
    float* out_c = out;                  // next_c  [B,R]
    float* out_h = out + B_ * R_;        // top_h   [B,R]
    float* out_l = out + 2 * B_ * R_;    // logsoft [B,V]

    float *attres_p, *nexth_p, *sums_p, *score1_p;
    cudaGetSymbolAddress((void**)&attres_p, g_attres);
    cudaGetSymbolAddress((void**)&nexth_p,  g_nexth);
    cudaGetSymbolAddress((void**)&sums_p,   g_sums);
    cudaGetSymbolAddress((void**)&score1_p, g_score1);

    __nv_bfloat16 *Wa2a_h, *Wa2a_l, *Wa2a1_h, *Wa2a1_l, *Wi_h, *Wi_l, *Wh_h, *Wh_l, *Wah_h, *Wah_l, *Wp_h, *Wp_l;
    cudaGetSymbolAddress((void**)&Wa2a_h,  g_Wa2a_h);  cudaGetSymbolAddress((void**)&Wa2a_l,  g_Wa2a_l);
    cudaGetSymbolAddress((void**)&Wa2a1_h, g_Wa2a1_h); cudaGetSymbolAddress((void**)&Wa2a1_l, g_Wa2a1_l);
    cudaGetSymbolAddress((void**)&Wi_h,    g_Wi_h);    cudaGetSymbolAddress((void**)&Wi_l,    g_Wi_l);
    cudaGetSymbolAddress((void**)&Wh_h,    g_Wh_h);    cudaGetSymbolAddress((void**)&Wh_l,    g_Wh_l);
    cudaGetSymbolAddress((void**)&Wah_h,   g_Wah_h);   cudaGetSymbolAddress((void**)&Wah_l,   g_Wah_l);
    cudaGetSymbolAddress((void**)&Wp_h,    g_Wp_h);    cudaGetSymbolAddress((void**)&Wp_l,    g_Wp_l);

    cudaFuncSetAttribute(attend_dual, cudaFuncAttributeMaxDynamicSharedMemorySize, SMEM_DUAL);
    cudaFuncSetAttribute(tc_gemm,     cudaFuncAttributeMaxDynamicSharedMemorySize, SMEM_GEMM);

    const dim3 blk(256);

    // ---- all weight conversions + gate bias in one launch ----
    conv_all<<<CONV_BLOCKS, blk>>>(W_a2a, W_a2a1, W_i2h, W_h2h, W_a2h, W_proj,
                                   b_i2h, b_h2h, b_a2h);

    // ---- ah0 (split-K) + fused dual attend GEMM ----
    sgemm_splitk<<<dim3(4, 4, 4), blk>>>(prev_h, W_h2a, b_h2a, B_, A_);
    attend_dual<<<dim3(4, (B_ * A_) / 128), blk, SMEM_DUAL>>>(
        att, Wa2a_h, Wa2a_l, Wa2a1_h, Wa2a1_l, b_a2a, W_d2d);
    attend_apply<<<B_, 1024>>>(att, attres_p, b_d2d, nullptr);

    // ---- LSTM gates (3 phases in grid.z) + cell ----
    tc_gemm<<<dim3(16, 2, 3), blk, SMEM_GEMM>>>(
        x, prev_h, attres_p,
        Wi_h, Wi_l, Wh_h, Wh_l, Wah_h, Wah_l,
        4 * R_, sums_p, 4 * R_, (size_t)B_ * 4 * R_);
    lstm_cell<<<(B_ * R_ / 4 + 255) / 256, blk>>>(prev_c, out_c);

    // ---- attend #1 finish (cheap) ----
    sgemm_splitk<<<dim3(4, 4, 4), blk>>>(nexth_p, W_h2a1, b_h2a1, B_, A_);
    attend1_score<<<(B_ * A_ * 32 + 255) / 256, blk>>>(b_a2a1, W_d2d1, b_d2d1);
    attend_apply<<<B_, 1024>>>(att, attres_p, nullptr, score1_p);

    // ---- top_h, projection, log_softmax ----
    add_toph<<<(B_ * R_ + 255) / 256, blk>>>(out_h);
    tc_gemm<<<dim3((V_ + 127) / 128, 2, 1), blk, SMEM_GEMM>>>(
        out_h, nullptr, nullptr,
        Wp_h, Wp_l, nullptr, nullptr, nullptr, nullptr,
        V_, out_l, V_, 0);
    log_softmax_kernel<<<B_, 512>>>(out_l, b_proj);
}